// round 6
// baseline (speedup 1.0000x reference)
#include <cuda_runtime.h>

#define BB 16
#define QN 128
#define KN 512
#define HN 128
#define DD 128
#define QT 4

// scratch
__device__ float g_kpt[BB * HN * KN];   // k-proj transposed [b][h][k]
__device__ float g_qh [BB * QN * HN];   // q-proj           [b][q][h]

__device__ __forceinline__ float ex2f(float x) {
    float r; asm("ex2.approx.f32 %0, %1;" : "=f"(r) : "f"(x)); return r;
}
__device__ __forceinline__ float tanhf_approx(float x) {
    float r; asm("tanh.approx.f32 %0, %1;" : "=f"(r) : "f"(x)); return r;
}

// ---------------------------------------------------------------------------
// proj_kernel: smem-tiled GEMM for both projections (unchanged).
// ---------------------------------------------------------------------------
__global__ __launch_bounds__(512) void proj_kernel(
    const float* __restrict__ keys, const float* __restrict__ queries,
    const float* __restrict__ Wk,   const float* __restrict__ Wq)
{
    extern __shared__ float dynsmem[];
    float* swt = dynsmem;                                  // [d][h] 128x128
    float (*srt)[68] = (float(*)[68])(dynsmem + DD * HN);  // [d][r] 128x68

    const int b   = blockIdx.y;
    const int tid = threadIdx.x;
    const bool isQ = blockIdx.x >= (KN / 64);
    const int r0  = (isQ ? (blockIdx.x - KN / 64) : blockIdx.x) * 64;
    const float* W    = isQ ? Wq : Wk;
    const float* rows = isQ ? (queries + (size_t)(b * QN + r0) * DD)
                            : (keys    + (size_t)(b * KN + r0) * DD);

    #pragma unroll
    for (int i = 0; i < 32; i++)
        swt[tid + i * 512] = W[tid + i * 512];
    #pragma unroll
    for (int i = 0; i < 16; i++) {
        int idx = tid + i * 512;
        srt[idx & 127][idx >> 7] = rows[idx];
    }
    __syncthreads();

    if (!isQ) {
        const int kt = tid & 7, ht = tid >> 3;
        float acc[8][2];
        #pragma unroll
        for (int i = 0; i < 8; i++) { acc[i][0] = 0.f; acc[i][1] = 0.f; }
        #pragma unroll 8
        for (int d = 0; d < DD; d++) {
            const float4* s4 = (const float4*)&srt[d][0];
            float4 ka = s4[kt * 2], kb = s4[kt * 2 + 1];
            float2 hw = ((const float2*)swt)[d * 64 + ht];
            float kvv[8] = {ka.x, ka.y, ka.z, ka.w, kb.x, kb.y, kb.z, kb.w};
            #pragma unroll
            for (int i = 0; i < 8; i++) {
                acc[i][0] = fmaf(kvv[i], hw.x, acc[i][0]);
                acc[i][1] = fmaf(kvv[i], hw.y, acc[i][1]);
            }
        }
        __syncthreads();
        #pragma unroll
        for (int j = 0; j < 2; j++)
            #pragma unroll
            for (int i = 0; i < 8; i++)
                srt[ht * 2 + j][kt * 8 + i] = acc[i][j];
        __syncthreads();
        #pragma unroll
        for (int i = 0; i < 4; i++) {
            int t = tid + i * 512;
            int h = t >> 4, k4 = t & 15;
            float4 v = *(const float4*)&srt[h][k4 * 4];
            *(float4*)&g_kpt[(size_t)(b * HN + h) * KN + r0 + k4 * 4] = v;
        }
    } else {
        const int qt = tid >> 4, ht2 = tid & 15;
        float acc[2][8];
        #pragma unroll
        for (int j = 0; j < 2; j++)
            #pragma unroll
            for (int i = 0; i < 8; i++) acc[j][i] = 0.f;
        #pragma unroll 8
        for (int d = 0; d < DD; d++) {
            float2 qv = *(const float2*)&srt[d][qt * 2];
            const float4* w4 = (const float4*)swt + d * 32 + ht2 * 2;
            float4 ha = w4[0], hb = w4[1];
            float hv[8] = {ha.x, ha.y, ha.z, ha.w, hb.x, hb.y, hb.z, hb.w};
            #pragma unroll
            for (int i = 0; i < 8; i++) {
                acc[0][i] = fmaf(qv.x, hv[i], acc[0][i]);
                acc[1][i] = fmaf(qv.y, hv[i], acc[1][i]);
            }
        }
        const int h = ht2 * 8;
        #pragma unroll
        for (int j = 0; j < 2; j++) {
            float* op = &g_qh[(size_t)(b * QN + r0 + qt * 2 + j) * HN + h];
            *(float4*)op       = make_float4(acc[j][0], acc[j][1], acc[j][2], acc[j][3]);
            *(float4*)(op + 4) = make_float4(acc[j][4], acc[j][5], acc[j][6], acc[j][7]);
        }
    }
}

// ---------------------------------------------------------------------------
// attn_kernel: one block per (b, 4-query tile). 512 threads (thread = key).
// grid = 512 blocks (2x round 4) for occupancy; MLP=8 load batching kept.
// ---------------------------------------------------------------------------
__global__ __launch_bounds__(512) void attn_kernel(
    const float* __restrict__ values, const int* __restrict__ valid_lens,
    const float* __restrict__ wv, float* __restrict__ out)
{
    __shared__ float sqh[HN][QT];       // [h][q]: one float4 per h
    __shared__ float swv[HN];
    __shared__ float sc[QT][KN];        // attn weights (8KB)
    __shared__ float part[QT * 512];    // split-K partials (8KB)
    __shared__ float redv[QT][16];
    __shared__ float smax[QT], sinvs[QT];

    const int q0 = blockIdx.x * QT, b = blockIdx.y;
    const int tid = threadIdx.x;
    const float LOG2E = 1.4426950408889634f;

    const int vlen = __ldg(&valid_lens[b]);

    if (tid < QT * DD) {
        int qq = tid >> 7, h = tid & 127;
        sqh[h][qq] = g_qh[(size_t)(b * QN + q0 + qq) * HN + h];
    }
    if (tid < HN) swv[tid] = wv[tid];
    __syncthreads();

    // ---- phase 1: scores. 8 kpt loads batched up-front per group ----
    const int k = tid;
    const float* kp = &g_kpt[(size_t)(b * HN) * KN + k];
    const float4* sqh4 = (const float4*)sqh;
    float s[QT] = {0.f, 0.f, 0.f, 0.f};

    #pragma unroll 1
    for (int hb = 0; hb < HN; hb += 8) {
        float kv[8];
        #pragma unroll
        for (int j = 0; j < 8; j++)
            kv[j] = kp[(size_t)(hb + j) * KN];
        #pragma unroll
        for (int j = 0; j < 8; j++) {
            const int h = hb + j;
            const float w = swv[h];
            float4 qa = sqh4[h];
            s[0] = fmaf(w, tanhf_approx(kv[j] + qa.x), s[0]);
            s[1] = fmaf(w, tanhf_approx(kv[j] + qa.y), s[1]);
            s[2] = fmaf(w, tanhf_approx(kv[j] + qa.z), s[2]);
            s[3] = fmaf(w, tanhf_approx(kv[j] + qa.w), s[3]);
        }
    }
    if (k >= vlen) {
        #pragma unroll
        for (int q = 0; q < QT; q++) s[q] = -1000000.0f;
    }

    // ---- masked softmax over 512 keys, 4 queries ----
    {
        float mx[QT];
        #pragma unroll
        for (int q = 0; q < QT; q++) mx[q] = s[q];
        #pragma unroll
        for (int off = 16; off; off >>= 1)
            #pragma unroll
            for (int q = 0; q < QT; q++)
                mx[q] = fmaxf(mx[q], __shfl_xor_sync(0xFFFFFFFFu, mx[q], off));
        if ((tid & 31) == 0)
            #pragma unroll
            for (int q = 0; q < QT; q++) redv[q][tid >> 5] = mx[q];
    }
    __syncthreads();
    if (tid < 64) {                      // 16 lanes per q
        int q = tid >> 4, w = tid & 15;
        float m = redv[q][w];
        #pragma unroll
        for (int off = 8; off; off >>= 1)
            m = fmaxf(m, __shfl_xor_sync(0xFFFFFFFFu, m, off));
        if (w == 0) smax[q] = m;
    }
    __syncthreads();

    float p[QT];
    {
        float sm[QT];
        #pragma unroll
        for (int q = 0; q < QT; q++) {
            p[q] = ex2f((s[q] - smax[q]) * LOG2E);
            sm[q] = p[q];
        }
        #pragma unroll
        for (int off = 16; off; off >>= 1)
            #pragma unroll
            for (int q = 0; q < QT; q++)
                sm[q] += __shfl_xor_sync(0xFFFFFFFFu, sm[q], off);
        if ((tid & 31) == 0)
            #pragma unroll
            for (int q = 0; q < QT; q++) redv[q][tid >> 5] = sm[q];
    }
    __syncthreads();
    if (tid < 64) {
        int q = tid >> 4, w = tid & 15;
        float t = redv[q][w];
        #pragma unroll
        for (int off = 8; off; off >>= 1)
            t += __shfl_xor_sync(0xFFFFFFFFu, t, off);
        if (w == 0) sinvs[q] = 1.0f / t;
    }
    __syncthreads();
    #pragma unroll
    for (int q = 0; q < QT; q++) sc[q][k] = p[q] * sinvs[q];
    __syncthreads();

    // ---- phase 2: out = attn @ values. 8 value loads batched per group ----
    {
        const int v = tid & 127, g = tid >> 7;
        const float* vp = values + (size_t)(b * KN + g * 128) * DD + v;
        float a[QT] = {0.f, 0.f, 0.f, 0.f};

        #pragma unroll 1
        for (int kk = 0; kk < 128; kk += 8) {
            float vv[8];
            #pragma unroll
            for (int j = 0; j < 8; j++)
                vv[j] = vp[(size_t)(kk + j) * DD];
            const int ki = g * 128 + kk;
            #pragma unroll
            for (int q = 0; q < QT; q++) {
                float4 c0 = *(const float4*)&sc[q][ki];
                float4 c1 = *(const float4*)&sc[q][ki + 4];
                a[q] = fmaf(c0.x, vv[0], a[q]);
                a[q] = fmaf(c0.y, vv[1], a[q]);
                a[q] = fmaf(c0.z, vv[2], a[q]);
                a[q] = fmaf(c0.w, vv[3], a[q]);
                a[q] = fmaf(c1.x, vv[4], a[q]);
                a[q] = fmaf(c1.y, vv[5], a[q]);
                a[q] = fmaf(c1.z, vv[6], a[q]);
                a[q] = fmaf(c1.w, vv[7], a[q]);
            }
        }
        #pragma unroll
        for (int q = 0; q < QT; q++) part[q * 512 + tid] = a[q];
    }
    __syncthreads();
    {
        int q = tid >> 7, v = tid & 127;
        const float* pq = &part[q * 512];
        out[(size_t)(b * QN + q0 + q) * DD + v] =
            (pq[v] + pq[128 + v]) + (pq[256 + v] + pq[384 + v]);
    }
}

extern "C" void kernel_launch(void* const* d_in, const int* in_sizes, int n_in,
                              void* d_out, int out_size)
{
    const float* queries = (const float*)d_in[0];
    const float* keys    = (const float*)d_in[1];
    const float* values  = (const float*)d_in[2];
    const int*   vlens   = (const int*)  d_in[3];
    const float* Wq      = (const float*)d_in[4];
    const float* Wk      = (const float*)d_in[5];
    const float* wv      = (const float*)d_in[6];
    float* out = (float*)d_out;

    const int proj_smem = (DD * HN + DD * 68) * sizeof(float);   // 100,352 B
    cudaFuncSetAttribute(proj_kernel,
                         cudaFuncAttributeMaxDynamicSharedMemorySize, proj_smem);

    proj_kernel<<<dim3(KN / 64 + QN / 64, BB), 512, proj_smem>>>(keys, queries, Wk, Wq);
    attn_kernel<<<dim3(QN / QT, BB), 512>>>(values, vlens, wv, out);
}

// round 7
// speedup vs baseline: 1.1812x; 1.1812x over previous
#include <cuda_runtime.h>

#define BB 16
#define QN 128
#define KN 512
#define HN 128
#define DD 128
#define QT 8

// scratch
__device__ float g_kpt[BB * HN * KN];   // k-proj transposed [b][h][k]
__device__ float g_qh [BB * QN * HN];   // q-proj           [b][q][h]

__device__ __forceinline__ float ex2f(float x) {
    float r; asm("ex2.approx.f32 %0, %1;" : "=f"(r) : "f"(x)); return r;
}
__device__ __forceinline__ float tanhf_approx(float x) {
    float r; asm("tanh.approx.f32 %0, %1;" : "=f"(r) : "f"(x)); return r;
}

// ---------------------------------------------------------------------------
// proj_kernel: smem-tiled GEMM for both projections (unchanged).
// ---------------------------------------------------------------------------
__global__ __launch_bounds__(512) void proj_kernel(
    const float* __restrict__ keys, const float* __restrict__ queries,
    const float* __restrict__ Wk,   const float* __restrict__ Wq)
{
    extern __shared__ float dynsmem[];
    float* swt = dynsmem;                                  // [d][h] 128x128
    float (*srt)[68] = (float(*)[68])(dynsmem + DD * HN);  // [d][r] 128x68

    const int b   = blockIdx.y;
    const int tid = threadIdx.x;
    const bool isQ = blockIdx.x >= (KN / 64);
    const int r0  = (isQ ? (blockIdx.x - KN / 64) : blockIdx.x) * 64;
    const float* W    = isQ ? Wq : Wk;
    const float* rows = isQ ? (queries + (size_t)(b * QN + r0) * DD)
                            : (keys    + (size_t)(b * KN + r0) * DD);

    #pragma unroll
    for (int i = 0; i < 32; i++)
        swt[tid + i * 512] = W[tid + i * 512];
    #pragma unroll
    for (int i = 0; i < 16; i++) {
        int idx = tid + i * 512;
        srt[idx & 127][idx >> 7] = rows[idx];
    }
    __syncthreads();

    if (!isQ) {
        const int kt = tid & 7, ht = tid >> 3;
        float acc[8][2];
        #pragma unroll
        for (int i = 0; i < 8; i++) { acc[i][0] = 0.f; acc[i][1] = 0.f; }
        #pragma unroll 8
        for (int d = 0; d < DD; d++) {
            const float4* s4 = (const float4*)&srt[d][0];
            float4 ka = s4[kt * 2], kb = s4[kt * 2 + 1];
            float2 hw = ((const float2*)swt)[d * 64 + ht];
            float kvv[8] = {ka.x, ka.y, ka.z, ka.w, kb.x, kb.y, kb.z, kb.w};
            #pragma unroll
            for (int i = 0; i < 8; i++) {
                acc[i][0] = fmaf(kvv[i], hw.x, acc[i][0]);
                acc[i][1] = fmaf(kvv[i], hw.y, acc[i][1]);
            }
        }
        __syncthreads();
        #pragma unroll
        for (int j = 0; j < 2; j++)
            #pragma unroll
            for (int i = 0; i < 8; i++)
                srt[ht * 2 + j][kt * 8 + i] = acc[i][j];
        __syncthreads();
        #pragma unroll
        for (int i = 0; i < 4; i++) {
            int t = tid + i * 512;
            int h = t >> 4, k4 = t & 15;
            float4 v = *(const float4*)&srt[h][k4 * 4];
            *(float4*)&g_kpt[(size_t)(b * HN + h) * KN + r0 + k4 * 4] = v;
        }
    } else {
        const int qt = tid >> 4, ht2 = tid & 15;
        float acc[2][8];
        #pragma unroll
        for (int j = 0; j < 2; j++)
            #pragma unroll
            for (int i = 0; i < 8; i++) acc[j][i] = 0.f;
        #pragma unroll 8
        for (int d = 0; d < DD; d++) {
            float2 qv = *(const float2*)&srt[d][qt * 2];
            const float4* w4 = (const float4*)swt + d * 32 + ht2 * 2;
            float4 ha = w4[0], hb = w4[1];
            float hv[8] = {ha.x, ha.y, ha.z, ha.w, hb.x, hb.y, hb.z, hb.w};
            #pragma unroll
            for (int i = 0; i < 8; i++) {
                acc[0][i] = fmaf(qv.x, hv[i], acc[0][i]);
                acc[1][i] = fmaf(qv.y, hv[i], acc[1][i]);
            }
        }
        const int h = ht2 * 8;
        #pragma unroll
        for (int j = 0; j < 2; j++) {
            float* op = &g_qh[(size_t)(b * QN + r0 + qt * 2 + j) * HN + h];
            *(float4*)op       = make_float4(acc[j][0], acc[j][1], acc[j][2], acc[j][3]);
            *(float4*)(op + 4) = make_float4(acc[j][4], acc[j][5], acc[j][6], acc[j][7]);
        }
    }
}

// ---------------------------------------------------------------------------
// attn_kernel: one block per (b, 8-query tile). 512 threads (thread = key).
// __launch_bounds__(512, 2): cap regs at 64 -> 2 blocks/SM -> grid 256 runs
// in a single wave with 32 warps/SM.
// ---------------------------------------------------------------------------
__global__ __launch_bounds__(512, 2) void attn_kernel(
    const float* __restrict__ values, const int* __restrict__ valid_lens,
    const float* __restrict__ wv, float* __restrict__ out)
{
    __shared__ float sqh[HN][QT];       // [h][q] q-projections
    __shared__ float swv[HN];
    __shared__ float sc[QT][KN];        // attn weights
    __shared__ float part[QT * 512];
    __shared__ float redv[QT][16];
    __shared__ float smax[QT], sinvs[QT];

    const int q0 = blockIdx.x * QT, b = blockIdx.y;
    const int tid = threadIdx.x;
    const float LOG2E = 1.4426950408889634f;

    const int vlen = __ldg(&valid_lens[b]);

    #pragma unroll
    for (int i = 0; i < 2; i++) {
        int t = tid + i * 512;
        int qq = t >> 7, h = t & 127;
        sqh[h][qq] = g_qh[(size_t)(b * QN + q0 + qq) * HN + h];
    }
    if (tid < HN) swv[tid] = wv[tid];
    __syncthreads();

    // ---- phase 1: scores. 8 kpt loads batched up-front per group ----
    const int k = tid;
    const float* kp = &g_kpt[(size_t)(b * HN) * KN + k];
    const float4* sqh4 = (const float4*)sqh;
    float s[QT];
    #pragma unroll
    for (int q = 0; q < QT; q++) s[q] = 0.f;

    #pragma unroll 1
    for (int hb = 0; hb < HN; hb += 8) {
        float kv[8];
        #pragma unroll
        for (int j = 0; j < 8; j++)
            kv[j] = kp[(size_t)(hb + j) * KN];
        #pragma unroll
        for (int j = 0; j < 8; j++) {
            const int h = hb + j;
            const float w = swv[h];
            float4 qa = sqh4[2 * h], qb = sqh4[2 * h + 1];
            s[0] = fmaf(w, tanhf_approx(kv[j] + qa.x), s[0]);
            s[1] = fmaf(w, tanhf_approx(kv[j] + qa.y), s[1]);
            s[2] = fmaf(w, tanhf_approx(kv[j] + qa.z), s[2]);
            s[3] = fmaf(w, tanhf_approx(kv[j] + qa.w), s[3]);
            s[4] = fmaf(w, tanhf_approx(kv[j] + qb.x), s[4]);
            s[5] = fmaf(w, tanhf_approx(kv[j] + qb.y), s[5]);
            s[6] = fmaf(w, tanhf_approx(kv[j] + qb.z), s[6]);
            s[7] = fmaf(w, tanhf_approx(kv[j] + qb.w), s[7]);
        }
    }
    if (k >= vlen) {
        #pragma unroll
        for (int q = 0; q < QT; q++) s[q] = -1000000.0f;
    }

    // ---- masked softmax over 512 keys, 8 queries ----
    {
        float mx[QT];
        #pragma unroll
        for (int q = 0; q < QT; q++) mx[q] = s[q];
        #pragma unroll
        for (int off = 16; off; off >>= 1)
            #pragma unroll
            for (int q = 0; q < QT; q++)
                mx[q] = fmaxf(mx[q], __shfl_xor_sync(0xFFFFFFFFu, mx[q], off));
        if ((tid & 31) == 0)
            #pragma unroll
            for (int q = 0; q < QT; q++) redv[q][tid >> 5] = mx[q];
    }
    __syncthreads();
    if (tid < 128) {
        int q = tid >> 4, w = tid & 15;
        float m = redv[q][w];
        #pragma unroll
        for (int off = 8; off; off >>= 1)
            m = fmaxf(m, __shfl_xor_sync(0xFFFFFFFFu, m, off));
        if (w == 0) smax[q] = m;
    }
    __syncthreads();

    float p[QT];
    {
        float sm[QT];
        #pragma unroll
        for (int q = 0; q < QT; q++) {
            p[q] = ex2f((s[q] - smax[q]) * LOG2E);
            sm[q] = p[q];
        }
        #pragma unroll
        for (int off = 16; off; off >>= 1)
            #pragma unroll
            for (int q = 0; q < QT; q++)
                sm[q] += __shfl_xor_sync(0xFFFFFFFFu, sm[q], off);
        if ((tid & 31) == 0)
            #pragma unroll
            for (int q = 0; q < QT; q++) redv[q][tid >> 5] = sm[q];
    }
    __syncthreads();
    if (tid < 128) {
        int q = tid >> 4, w = tid & 15;
        float t = redv[q][w];
        #pragma unroll
        for (int off = 8; off; off >>= 1)
            t += __shfl_xor_sync(0xFFFFFFFFu, t, off);
        if (w == 0) sinvs[q] = 1.0f / t;
    }
    __syncthreads();
    #pragma unroll
    for (int q = 0; q < QT; q++) sc[q][k] = p[q] * sinvs[q];
    __syncthreads();

    // ---- phase 2: out = attn @ values. 8 value loads batched per group ----
    {
        const int v = tid & 127, g = tid >> 7;
        const float* vp = values + (size_t)(b * KN + g * 128) * DD + v;
        float a[QT];
        #pragma unroll
        for (int q = 0; q < QT; q++) a[q] = 0.f;

        #pragma unroll 1
        for (int kk = 0; kk < 128; kk += 8) {
            float vv[8];
            #pragma unroll
            for (int j = 0; j < 8; j++)
                vv[j] = vp[(size_t)(kk + j) * DD];
            const int ki = g * 128 + kk;
            #pragma unroll
            for (int q = 0; q < QT; q++) {
                float4 c0 = *(const float4*)&sc[q][ki];
                float4 c1 = *(const float4*)&sc[q][ki + 4];
                a[q] = fmaf(c0.x, vv[0], a[q]);
                a[q] = fmaf(c0.y, vv[1], a[q]);
                a[q] = fmaf(c0.z, vv[2], a[q]);
                a[q] = fmaf(c0.w, vv[3], a[q]);
                a[q] = fmaf(c1.x, vv[4], a[q]);
                a[q] = fmaf(c1.y, vv[5], a[q]);
                a[q] = fmaf(c1.z, vv[6], a[q]);
                a[q] = fmaf(c1.w, vv[7], a[q]);
            }
        }
        #pragma unroll
        for (int q = 0; q < QT; q++) part[q * 512 + tid] = a[q];
    }
    __syncthreads();
    #pragma unroll
    for (int i = 0; i < 2; i++) {
        int t = tid + i * 512;
        int q = t >> 7, v = t & 127;
        const float* pq = &part[q * 512];
        out[(size_t)(b * QN + q0 + q) * DD + v] =
            (pq[v] + pq[128 + v]) + (pq[256 + v] + pq[384 + v]);
    }
}

extern "C" void kernel_launch(void* const* d_in, const int* in_sizes, int n_in,
                              void* d_out, int out_size)
{
    const float* queries = (const float*)d_in[0];
    const float* keys    = (const float*)d_in[1];
    const float* values  = (const float*)d_in[2];
    const int*   vlens   = (const int*)  d_in[3];
    const float* Wq      = (const float*)d_in[4];
    const float* Wk      = (const float*)d_in[5];
    const float* wv      = (const float*)d_in[6];
    float* out = (float*)d_out;

    const int proj_smem = (DD * HN + DD * 68) * sizeof(float);   // 100,352 B
    cudaFuncSetAttribute(proj_kernel,
                         cudaFuncAttributeMaxDynamicSharedMemorySize, proj_smem);

    proj_kernel<<<dim3(KN / 64 + QN / 64, BB), 512, proj_smem>>>(keys, queries, Wk, Wq);
    attn_kernel<<<dim3(QN / QT, BB), 512>>>(values, vlens, wv, out);
}

// round 8
// speedup vs baseline: 1.2994x; 1.1001x over previous
#include <cuda_runtime.h>

#define BB 16
#define QN 128
#define KN 512
#define HN 128
#define DD 128
#define QT 8
#define RT 32          // proj row-tile

// scratch
__device__ float g_kpt[BB * HN * KN];   // k-proj transposed [b][h][k]
__device__ float g_qh [BB * QN * HN];   // q-proj           [b][q][h]

__device__ __forceinline__ float ex2f(float x) {
    float r; asm("ex2.approx.f32 %0, %1;" : "=f"(r) : "f"(x)); return r;
}
// pack two f32 -> f16x2  (hi = a, lo = b)
__device__ __forceinline__ unsigned pack_h2(float hi, float lo) {
    unsigned r; asm("cvt.rn.f16x2.f32 %0, %1, %2;" : "=r"(r) : "f"(hi), "f"(lo)); return r;
}
__device__ __forceinline__ unsigned hadd2(unsigned a, unsigned b) {
    unsigned r; asm("add.f16x2 %0, %1, %2;" : "=r"(r) : "r"(a), "r"(b)); return r;
}
__device__ __forceinline__ unsigned tanh2(unsigned x) {
    unsigned r; asm("tanh.approx.f16x2 %0, %1;" : "=r"(r) : "r"(x)); return r;
}
__device__ __forceinline__ void unpack_h2(unsigned x, float& lo, float& hi) {
    asm("{\n\t.reg .f16 l, h;\n\tmov.b32 {l, h}, %2;\n\t"
        "cvt.f32.f16 %0, l;\n\tcvt.f32.f16 %1, h;\n\t}"
        : "=f"(lo), "=f"(hi) : "r"(x));
}

// ---------------------------------------------------------------------------
// proj_kernel: smem-tiled GEMM, 32-row tiles -> grid (20,16)=320 blocks.
//   blockIdx.x < 16 : 32-key tile  -> g_kpt[b][h][k] (transposed store)
//   blockIdx.x >= 16: 32-query tile-> g_qh[b][q][h]
// ---------------------------------------------------------------------------
__global__ __launch_bounds__(512) void proj_kernel(
    const float* __restrict__ keys, const float* __restrict__ queries,
    const float* __restrict__ Wk,   const float* __restrict__ Wq)
{
    extern __shared__ float dynsmem[];
    float* swt = dynsmem;                                  // [d][h] 128x128
    float (*srt)[36] = (float(*)[36])(dynsmem + DD * HN);  // [d][r] 128x36

    const int b   = blockIdx.y;
    const int tid = threadIdx.x;
    const bool isQ = blockIdx.x >= (KN / RT);
    const int r0  = (isQ ? (blockIdx.x - KN / RT) : blockIdx.x) * RT;
    const float* W    = isQ ? Wq : Wk;
    const float* rows = isQ ? (queries + (size_t)(b * QN + r0) * DD)
                            : (keys    + (size_t)(b * KN + r0) * DD);

    #pragma unroll
    for (int i = 0; i < 32; i++)
        swt[tid + i * 512] = W[tid + i * 512];
    #pragma unroll
    for (int i = 0; i < 8; i++) {                 // 32 rows x 128 d
        int idx = tid + i * 512;
        srt[idx & 127][idx >> 7] = rows[idx];
    }
    __syncthreads();

    if (!isQ) {
        // 8 keys x 1 h per thread: kt = tid&3 (8-key group), ht = tid>>2
        const int kt = tid & 3, ht = tid >> 2;
        float acc[8];
        #pragma unroll
        for (int i = 0; i < 8; i++) acc[i] = 0.f;
        #pragma unroll 8
        for (int d = 0; d < DD; d++) {
            const float4* s4 = (const float4*)&srt[d][0];
            float4 ka = s4[kt * 2], kb = s4[kt * 2 + 1];
            float w = swt[d * HN + ht];
            acc[0] = fmaf(ka.x, w, acc[0]);
            acc[1] = fmaf(ka.y, w, acc[1]);
            acc[2] = fmaf(ka.z, w, acc[2]);
            acc[3] = fmaf(ka.w, w, acc[3]);
            acc[4] = fmaf(kb.x, w, acc[4]);
            acc[5] = fmaf(kb.y, w, acc[5]);
            acc[6] = fmaf(kb.z, w, acc[6]);
            acc[7] = fmaf(kb.w, w, acc[7]);
        }
        __syncthreads();
        #pragma unroll
        for (int i = 0; i < 8; i++)
            srt[ht][kt * 8 + i] = acc[i];          // srt reused as [h][k]
        __syncthreads();
        #pragma unroll
        for (int i = 0; i < 2; i++) {
            int t = tid + i * 512;                 // 1024 float4
            int h = t >> 3, k4 = t & 7;
            float4 v = *(const float4*)&srt[h][k4 * 4];
            *(float4*)&g_kpt[(size_t)(b * HN + h) * KN + r0 + k4 * 4] = v;
        }
    } else {
        // 2 q x 4 h per thread: qt = tid&15, ht2 = tid>>4
        const int qt = tid & 15, ht2 = tid >> 4;
        float acc[2][4];
        #pragma unroll
        for (int j = 0; j < 2; j++)
            #pragma unroll
            for (int i = 0; i < 4; i++) acc[j][i] = 0.f;
        #pragma unroll 8
        for (int d = 0; d < DD; d++) {
            float2 qv = *(const float2*)&srt[d][qt * 2];
            float4 w4 = *(const float4*)&swt[d * HN + ht2 * 4];
            acc[0][0] = fmaf(qv.x, w4.x, acc[0][0]);
            acc[0][1] = fmaf(qv.x, w4.y, acc[0][1]);
            acc[0][2] = fmaf(qv.x, w4.z, acc[0][2]);
            acc[0][3] = fmaf(qv.x, w4.w, acc[0][3]);
            acc[1][0] = fmaf(qv.y, w4.x, acc[1][0]);
            acc[1][1] = fmaf(qv.y, w4.y, acc[1][1]);
            acc[1][2] = fmaf(qv.y, w4.z, acc[1][2]);
            acc[1][3] = fmaf(qv.y, w4.w, acc[1][3]);
        }
        #pragma unroll
        for (int j = 0; j < 2; j++) {
            float* op = &g_qh[(size_t)(b * QN + r0 + qt * 2 + j) * HN + ht2 * 4];
            *(float4*)op = make_float4(acc[j][0], acc[j][1], acc[j][2], acc[j][3]);
        }
    }
}

// ---------------------------------------------------------------------------
// attn_kernel: one block per (b, 8-query tile). 512 threads (thread = key).
// f16x2 tanh: one MUFU per 2 queries; f32 accumulation.
// ---------------------------------------------------------------------------
__global__ __launch_bounds__(512, 2) void attn_kernel(
    const float* __restrict__ values, const int* __restrict__ valid_lens,
    const float* __restrict__ wv, float* __restrict__ out)
{
    __shared__ unsigned sqh2[HN][4];    // [h][pair]: f16x2 {q(2p+1), q(2p)}
    __shared__ float swv[HN];
    __shared__ float sc[QT][KN];        // attn weights
    __shared__ float part[QT * 512];
    __shared__ float redv[QT][16];
    __shared__ float smax[QT], sinvs[QT];

    const int q0 = blockIdx.x * QT, b = blockIdx.y;
    const int tid = threadIdx.x;
    const float LOG2E = 1.4426950408889634f;

    const int vlen = __ldg(&valid_lens[b]);

    {   // stage q-projection pairs as f16x2
        int h = tid >> 2, p = tid & 3;
        const float* qb = &g_qh[(size_t)(b * QN + q0 + 2 * p) * HN + h];
        float qlo = qb[0], qhi = qb[HN];
        sqh2[h][p] = pack_h2(qhi, qlo);
    }
    if (tid < HN) swv[tid] = wv[tid];
    __syncthreads();

    // ---- phase 1: scores. 8 kpt loads batched up-front per group ----
    const int k = tid;
    const float* kp = &g_kpt[(size_t)(b * HN) * KN + k];
    float s[QT];
    #pragma unroll
    for (int q = 0; q < QT; q++) s[q] = 0.f;

    #pragma unroll 1
    for (int hb = 0; hb < HN; hb += 8) {
        float kv[8];
        #pragma unroll
        for (int j = 0; j < 8; j++)
            kv[j] = kp[(size_t)(hb + j) * KN];
        #pragma unroll
        for (int j = 0; j < 8; j++) {
            const int h = hb + j;
            const float w = swv[h];
            uint4 qp = *(const uint4*)&sqh2[h][0];
            unsigned kv2 = pack_h2(kv[j], kv[j]);
            float lo, hi;
            unpack_h2(tanh2(hadd2(kv2, qp.x)), lo, hi);
            s[0] = fmaf(w, lo, s[0]); s[1] = fmaf(w, hi, s[1]);
            unpack_h2(tanh2(hadd2(kv2, qp.y)), lo, hi);
            s[2] = fmaf(w, lo, s[2]); s[3] = fmaf(w, hi, s[3]);
            unpack_h2(tanh2(hadd2(kv2, qp.z)), lo, hi);
            s[4] = fmaf(w, lo, s[4]); s[5] = fmaf(w, hi, s[5]);
            unpack_h2(tanh2(hadd2(kv2, qp.w)), lo, hi);
            s[6] = fmaf(w, lo, s[6]); s[7] = fmaf(w, hi, s[7]);
        }
    }
    if (k >= vlen) {
        #pragma unroll
        for (int q = 0; q < QT; q++) s[q] = -1000000.0f;
    }

    // ---- masked softmax over 512 keys, 8 queries ----
    {
        float mx[QT];
        #pragma unroll
        for (int q = 0; q < QT; q++) mx[q] = s[q];
        #pragma unroll
        for (int off = 16; off; off >>= 1)
            #pragma unroll
            for (int q = 0; q < QT; q++)
                mx[q] = fmaxf(mx[q], __shfl_xor_sync(0xFFFFFFFFu, mx[q], off));
        if ((tid & 31) == 0)
            #pragma unroll
            for (int q = 0; q < QT; q++) redv[q][tid >> 5] = mx[q];
    }
    __syncthreads();
    if (tid < 128) {
        int q = tid >> 4, w = tid & 15;
        float m = redv[q][w];
        #pragma unroll
        for (int off = 8; off; off >>= 1)
            m = fmaxf(m, __shfl_xor_sync(0xFFFFFFFFu, m, off));
        if (w == 0) smax[q] = m;
    }
    __syncthreads();

    float p[QT];
    {
        float sm[QT];
        #pragma unroll
        for (int q = 0; q < QT; q++) {
            p[q] = ex2f((s[q] - smax[q]) * LOG2E);
            sm[q] = p[q];
        }
        #pragma unroll
        for (int off = 16; off; off >>= 1)
            #pragma unroll
            for (int q = 0; q < QT; q++)
                sm[q] += __shfl_xor_sync(0xFFFFFFFFu, sm[q], off);
        if ((tid & 31) == 0)
            #pragma unroll
            for (int q = 0; q < QT; q++) redv[q][tid >> 5] = sm[q];
    }
    __syncthreads();
    if (tid < 128) {
        int q = tid >> 4, w = tid & 15;
        float t = redv[q][w];
        #pragma unroll
        for (int off = 8; off; off >>= 1)
            t += __shfl_xor_sync(0xFFFFFFFFu, t, off);
        if (w == 0) sinvs[q] = 1.0f / t;
    }
    __syncthreads();
    #pragma unroll
    for (int q = 0; q < QT; q++) sc[q][k] = p[q] * sinvs[q];
    __syncthreads();

    // ---- phase 2: out = attn @ values. 8 value loads batched per group ----
    {
        const int v = tid & 127, g = tid >> 7;
        const float* vp = values + (size_t)(b * KN + g * 128) * DD + v;
        float a[QT];
        #pragma unroll
        for (int q = 0; q < QT; q++) a[q] = 0.f;

        #pragma unroll 1
        for (int kk = 0; kk < 128; kk += 8) {
            float vv[8];
            #pragma unroll
            for (int j = 0; j < 8; j++)
                vv[j] = vp[(size_t)(kk + j) * DD];
            const int ki = g * 128 + kk;
            #pragma unroll
            for (int q = 0; q < QT; q++) {
                float4 c0 = *(const float4*)&sc[q][ki];
                float4 c1 = *(const float4*)&sc[q][ki + 4];
                a[q] = fmaf(c0.x, vv[0], a[q]);
                a[q] = fmaf(c0.y, vv[1], a[q]);
                a[q] = fmaf(c0.z, vv[2], a[q]);
                a[q] = fmaf(c0.w, vv[3], a[q]);
                a[q] = fmaf(c1.x, vv[4], a[q]);
                a[q] = fmaf(c1.y, vv[5], a[q]);
                a[q] = fmaf(c1.z, vv[6], a[q]);
                a[q] = fmaf(c1.w, vv[7], a[q]);
            }
        }
        #pragma unroll
        for (int q = 0; q < QT; q++) part[q * 512 + tid] = a[q];
    }
    __syncthreads();
    #pragma unroll
    for (int i = 0; i < 2; i++) {
        int t = tid + i * 512;
        int q = t >> 7, v = t & 127;
        const float* pq = &part[q * 512];
        out[(size_t)(b * QN + q0 + q) * DD + v] =
            (pq[v] + pq[128 + v]) + (pq[256 + v] + pq[384 + v]);
    }
}

extern "C" void kernel_launch(void* const* d_in, const int* in_sizes, int n_in,
                              void* d_out, int out_size)
{
    const float* queries = (const float*)d_in[0];
    const float* keys    = (const float*)d_in[1];
    const float* values  = (const float*)d_in[2];
    const int*   vlens   = (const int*)  d_in[3];
    const float* Wq      = (const float*)d_in[4];
    const float* Wk      = (const float*)d_in[5];
    const float* wv      = (const float*)d_in[6];
    float* out = (float*)d_out;

    const int proj_smem = (DD * HN + DD * 36) * sizeof(float);   // 83,968 B
    cudaFuncSetAttribute(proj_kernel,
                         cudaFuncAttributeMaxDynamicSharedMemorySize, proj_smem);

    proj_kernel<<<dim3(KN / RT + QN / RT, BB), 512, proj_smem>>>(keys, queries, Wk, Wq);
    attn_kernel<<<dim3(QN / QT, BB), 512>>>(values, vlens, wv, out);
}

// round 10
// speedup vs baseline: 1.3031x; 1.0028x over previous
#include <cuda_runtime.h>

#define BB 16
#define QN 128
#define KN 512
#define HN 128
#define DD 128
#define QT 8
#define RT 32          // proj row-tile
#define HC 16          // h-chunk size for smem staging

// scratch
__device__ float g_kpt[BB * HN * KN];   // k-proj transposed [b][h][k]
__device__ float g_qh [BB * QN * HN];   // q-proj           [b][q][h]

__device__ __forceinline__ float ex2f(float x) {
    float r; asm("ex2.approx.f32 %0, %1;" : "=f"(r) : "f"(x)); return r;
}
__device__ __forceinline__ unsigned pack_h2(float hi, float lo) {
    unsigned r; asm("cvt.rn.f16x2.f32 %0, %1, %2;" : "=r"(r) : "f"(hi), "f"(lo)); return r;
}
__device__ __forceinline__ unsigned hadd2(unsigned a, unsigned b) {
    unsigned r; asm("add.f16x2 %0, %1, %2;" : "=r"(r) : "r"(a), "r"(b)); return r;
}
__device__ __forceinline__ unsigned tanh2(unsigned x) {
    unsigned r; asm("tanh.approx.f16x2 %0, %1;" : "=r"(r) : "r"(x)); return r;
}
__device__ __forceinline__ void unpack_h2(unsigned x, float& lo, float& hi) {
    asm("{\n\t.reg .f16 l, h;\n\tmov.b32 {l, h}, %2;\n\t"
        "cvt.f32.f16 %0, l;\n\tcvt.f32.f16 %1, h;\n\t}"
        : "=f"(lo), "=f"(hi) : "r"(x));
}
__device__ __forceinline__ unsigned smem_u32(const void* p) {
    return (unsigned)__cvta_generic_to_shared(p);
}
__device__ __forceinline__ void cp_async16(unsigned dst, const void* src) {
    asm volatile("cp.async.cg.shared.global [%0], [%1], 16;" :: "r"(dst), "l"(src));
}

// ---------------------------------------------------------------------------
// proj_kernel: smem-tiled GEMM, 32-row tiles (unchanged from R8).
// ---------------------------------------------------------------------------
__global__ __launch_bounds__(512) void proj_kernel(
    const float* __restrict__ keys, const float* __restrict__ queries,
    const float* __restrict__ Wk,   const float* __restrict__ Wq)
{
    extern __shared__ float dynsmem[];
    float* swt = dynsmem;                                  // [d][h] 128x128
    float (*srt)[36] = (float(*)[36])(dynsmem + DD * HN);  // [d][r] 128x36

    const int b   = blockIdx.y;
    const int tid = threadIdx.x;
    const bool isQ = blockIdx.x >= (KN / RT);
    const int r0  = (isQ ? (blockIdx.x - KN / RT) : blockIdx.x) * RT;
    const float* W    = isQ ? Wq : Wk;
    const float* rows = isQ ? (queries + (size_t)(b * QN + r0) * DD)
                            : (keys    + (size_t)(b * KN + r0) * DD);

    #pragma unroll
    for (int i = 0; i < 32; i++)
        swt[tid + i * 512] = W[tid + i * 512];
    #pragma unroll
    for (int i = 0; i < 8; i++) {
        int idx = tid + i * 512;
        srt[idx & 127][idx >> 7] = rows[idx];
    }
    __syncthreads();

    if (!isQ) {
        const int kt = tid & 3, ht = tid >> 2;
        float acc[8];
        #pragma unroll
        for (int i = 0; i < 8; i++) acc[i] = 0.f;
        #pragma unroll 8
        for (int d = 0; d < DD; d++) {
            const float4* s4 = (const float4*)&srt[d][0];
            float4 ka = s4[kt * 2], kb = s4[kt * 2 + 1];
            float w = swt[d * HN + ht];
            acc[0] = fmaf(ka.x, w, acc[0]);
            acc[1] = fmaf(ka.y, w, acc[1]);
            acc[2] = fmaf(ka.z, w, acc[2]);
            acc[3] = fmaf(ka.w, w, acc[3]);
            acc[4] = fmaf(kb.x, w, acc[4]);
            acc[5] = fmaf(kb.y, w, acc[5]);
            acc[6] = fmaf(kb.z, w, acc[6]);
            acc[7] = fmaf(kb.w, w, acc[7]);
        }
        __syncthreads();
        #pragma unroll
        for (int i = 0; i < 8; i++)
            srt[ht][kt * 8 + i] = acc[i];
        __syncthreads();
        #pragma unroll
        for (int i = 0; i < 2; i++) {
            int t = tid + i * 512;
            int h = t >> 3, k4 = t & 7;
            float4 v = *(const float4*)&srt[h][k4 * 4];
            *(float4*)&g_kpt[(size_t)(b * HN + h) * KN + r0 + k4 * 4] = v;
        }
    } else {
        const int qt = tid & 15, ht2 = tid >> 4;
        float acc[2][4];
        #pragma unroll
        for (int j = 0; j < 2; j++)
            #pragma unroll
            for (int i = 0; i < 4; i++) acc[j][i] = 0.f;
        #pragma unroll 8
        for (int d = 0; d < DD; d++) {
            float2 qv = *(const float2*)&srt[d][qt * 2];
            float4 w4 = *(const float4*)&swt[d * HN + ht2 * 4];
            acc[0][0] = fmaf(qv.x, w4.x, acc[0][0]);
            acc[0][1] = fmaf(qv.x, w4.y, acc[0][1]);
            acc[0][2] = fmaf(qv.x, w4.z, acc[0][2]);
            acc[0][3] = fmaf(qv.x, w4.w, acc[0][3]);
            acc[1][0] = fmaf(qv.y, w4.x, acc[1][0]);
            acc[1][1] = fmaf(qv.y, w4.y, acc[1][1]);
            acc[1][2] = fmaf(qv.y, w4.z, acc[1][2]);
            acc[1][3] = fmaf(qv.y, w4.w, acc[1][3]);
        }
        #pragma unroll
        for (int j = 0; j < 2; j++) {
            float* op = &g_qh[(size_t)(b * QN + r0 + qt * 2 + j) * HN + ht2 * 4];
            *(float4*)op = make_float4(acc[j][0], acc[j][1], acc[j][2], acc[j][3]);
        }
    }
}

// ---------------------------------------------------------------------------
// attn_kernel: one block per (b, 8-query tile). 512 threads (thread = key).
// Phase 1 reads kpt through a cp.async double-buffered smem pipeline.
// Dynamic smem: kbuf[2][16][512] (64KB, aliased by part) + sc (16KB) + misc.
// ---------------------------------------------------------------------------
__global__ __launch_bounds__(512, 2) void attn_kernel(
    const float* __restrict__ values, const int* __restrict__ valid_lens,
    const float* __restrict__ wv, float* __restrict__ out)
{
    extern __shared__ float dsm[];
    float*    kbuf = dsm;                          // 2*HC*512 = 16384 floats
    float*    sc   = dsm + 2 * HC * 512;           // 4096 floats
    unsigned* sqh2 = (unsigned*)(sc + QT * KN);    // 512 u32
    float*    swv  = (float*)(sqh2 + HN * 4);      // 128
    float*    redv = swv + HN;                     // 128 (QT x 16)
    float*    smax = redv + QT * 16;               // 8
    float*    sinv = smax + QT;                    // 8
    float*    part = kbuf;                         // alias (phase 2 only)

    const int q0 = blockIdx.x * QT, b = blockIdx.y;
    const int tid = threadIdx.x;
    const float LOG2E = 1.4426950408889634f;

    const int vlen = __ldg(&valid_lens[b]);

    {   // stage q-projection pairs as f16x2
        int h = tid >> 2, p = tid & 3;
        const float* qb = &g_qh[(size_t)(b * QN + q0 + 2 * p) * HN + h];
        float qlo = qb[0], qhi = qb[HN];
        sqh2[h * 4 + p] = pack_h2(qhi, qlo);
    }
    if (tid < HN) swv[tid] = wv[tid];

    // ---- phase 1: pipelined over 8 chunks of 16 h ----
    const int k = tid;
    const float* kbase = &g_kpt[(size_t)(b * HN) * KN];   // chunk c = 8192 floats at c*8192
    float s[QT];
    #pragma unroll
    for (int q = 0; q < QT; q++) s[q] = 0.f;

    // prefetch chunk 0
    {
        const float4* src = (const float4*)(kbase) + tid;
        unsigned dst = smem_u32(kbuf) + tid * 16;
        #pragma unroll
        for (int i = 0; i < 4; i++)
            cp_async16(dst + i * 512 * 16, src + i * 512);
        asm volatile("cp.async.commit_group;");
    }

    #pragma unroll 1
    for (int c = 0; c < HN / HC; c++) {
        if (c < HN / HC - 1) {   // prefetch chunk c+1 into other buffer
            const float4* src = (const float4*)(kbase + (size_t)(c + 1) * HC * KN) + tid;
            unsigned dst = smem_u32(kbuf + ((c + 1) & 1) * HC * KN) + tid * 16;
            #pragma unroll
            for (int i = 0; i < 4; i++)
                cp_async16(dst + i * 512 * 16, src + i * 512);
            asm volatile("cp.async.commit_group;");
            asm volatile("cp.async.wait_group 1;");
        } else {
            asm volatile("cp.async.wait_group 0;");
        }
        __syncthreads();

        const float* kb = kbuf + (c & 1) * HC * KN;
        #pragma unroll
        for (int j = 0; j < HC; j++) {
            const int h = c * HC + j;
            const float kv = kb[j * KN + k];
            const float w = swv[h];
            uint4 qp = *(const uint4*)&sqh2[h * 4];
            unsigned kv2 = pack_h2(kv, kv);
            float lo, hi;
            unpack_h2(tanh2(hadd2(kv2, qp.x)), lo, hi);
            s[0] = fmaf(w, lo, s[0]); s[1] = fmaf(w, hi, s[1]);
            unpack_h2(tanh2(hadd2(kv2, qp.y)), lo, hi);
            s[2] = fmaf(w, lo, s[2]); s[3] = fmaf(w, hi, s[3]);
            unpack_h2(tanh2(hadd2(kv2, qp.z)), lo, hi);
            s[4] = fmaf(w, lo, s[4]); s[5] = fmaf(w, hi, s[5]);
            unpack_h2(tanh2(hadd2(kv2, qp.w)), lo, hi);
            s[6] = fmaf(w, lo, s[6]); s[7] = fmaf(w, hi, s[7]);
        }
        __syncthreads();   // all threads done reading this buffer
    }

    if (k >= vlen) {
        #pragma unroll
        for (int q = 0; q < QT; q++) s[q] = -1000000.0f;
    }

    // ---- masked softmax over 512 keys, 8 queries ----
    {
        float mx[QT];
        #pragma unroll
        for (int q = 0; q < QT; q++) mx[q] = s[q];
        #pragma unroll
        for (int off = 16; off; off >>= 1)
            #pragma unroll
            for (int q = 0; q < QT; q++)
                mx[q] = fmaxf(mx[q], __shfl_xor_sync(0xFFFFFFFFu, mx[q], off));
        if ((tid & 31) == 0)
            #pragma unroll
            for (int q = 0; q < QT; q++) redv[q * 16 + (tid >> 5)] = mx[q];
    }
    __syncthreads();
    if (tid < 128) {
        int q = tid >> 4, w = tid & 15;
        float m = redv[q * 16 + w];
        #pragma unroll
        for (int off = 8; off; off >>= 1)
            m = fmaxf(m, __shfl_xor_sync(0xFFFFFFFFu, m, off));
        if (w == 0) smax[q] = m;
    }
    __syncthreads();

    float p[QT];
    {
        float sm[QT];
        #pragma unroll
        for (int q = 0; q < QT; q++) {
            p[q] = ex2f((s[q] - smax[q]) * LOG2E);
            sm[q] = p[q];
        }
        #pragma unroll
        for (int off = 16; off; off >>= 1)
            #pragma unroll
            for (int q = 0; q < QT; q++)
                sm[q] += __shfl_xor_sync(0xFFFFFFFFu, sm[q], off);
        if ((tid & 31) == 0)
            #pragma unroll
            for (int q = 0; q < QT; q++) redv[q * 16 + (tid >> 5)] = sm[q];
    }
    __syncthreads();
    if (tid < 128) {
        int q = tid >> 4, w = tid & 15;
        float t = redv[q * 16 + w];
        #pragma unroll
        for (int off = 8; off; off >>= 1)
            t += __shfl_xor_sync(0xFFFFFFFFu, t, off);
        if (w == 0) sinv[q] = 1.0f / t;
    }
    __syncthreads();
    #pragma unroll
    for (int q = 0; q < QT; q++) sc[q * KN + k] = p[q] * sinv[q];
    __syncthreads();

    // ---- phase 2: out = attn @ values. 8 value loads batched per group ----
    {
        const int v = tid & 127, g = tid >> 7;
        const float* vp = values + (size_t)(b * KN + g * 128) * DD + v;
        float a[QT];
        #pragma unroll
        for (int q = 0; q < QT; q++) a[q] = 0.f;

        #pragma unroll 1
        for (int kk = 0; kk < 128; kk += 8) {
            float vv[8];
            #pragma unroll
            for (int j = 0; j < 8; j++)
                vv[j] = vp[(size_t)(kk + j) * DD];
            const int ki = g * 128 + kk;
            #pragma unroll
            for (int q = 0; q < QT; q++) {
                float4 c0 = *(const float4*)&sc[q * KN + ki];
                float4 c1 = *(const float4*)&sc[q * KN + ki + 4];
                a[q] = fmaf(c0.x, vv[0], a[q]);
                a[q] = fmaf(c0.y, vv[1], a[q]);
                a[q] = fmaf(c0.z, vv[2], a[q]);
                a[q] = fmaf(c0.w, vv[3], a[q]);
                a[q] = fmaf(c1.x, vv[4], a[q]);
                a[q] = fmaf(c1.y, vv[5], a[q]);
                a[q] = fmaf(c1.z, vv[6], a[q]);
                a[q] = fmaf(c1.w, vv[7], a[q]);
            }
        }
        #pragma unroll
        for (int q = 0; q < QT; q++) part[q * 512 + tid] = a[q];
    }
    __syncthreads();
    #pragma unroll
    for (int i = 0; i < 2; i++) {
        int t = tid + i * 512;
        int q = t >> 7, v = t & 127;
        const float* pq = &part[q * 512];
        out[(size_t)(b * QN + q0 + q) * DD + v] =
            (pq[v] + pq[128 + v]) + (pq[256 + v] + pq[384 + v]);
    }
}

extern "C" void kernel_launch(void* const* d_in, const int* in_sizes, int n_in,
                              void* d_out, int out_size)
{
    const float* queries = (const float*)d_in[0];
    const float* keys    = (const float*)d_in[1];
    const float* values  = (const float*)d_in[2];
    const int*   vlens   = (const int*)  d_in[3];
    const float* Wq      = (const float*)d_in[4];
    const float* Wk      = (const float*)d_in[5];
    const float* wv      = (const float*)d_in[6];
    float* out = (float*)d_out;

    const int proj_smem = (DD * HN + DD * 36) * sizeof(float);   // 83,968 B
    cudaFuncSetAttribute(proj_kernel,
                         cudaFuncAttributeMaxDynamicSharedMemorySize, proj_smem);

    const int attn_smem = (2 * HC * 512 + QT * KN + 512 + HN + QT * 16 + 2 * QT + 32)
                          * sizeof(float);                        // ~84 KB
    cudaFuncSetAttribute(attn_kernel,
                         cudaFuncAttributeMaxDynamicSharedMemorySize, attn_smem);

    proj_kernel<<<dim3(KN / RT + QN / RT, BB), 512, proj_smem>>>(keys, queries, Wk, Wq);
    attn_kernel<<<dim3(QN / QT, BB), 512, attn_smem>>>(values, vlens, wv, out);
}

// round 11
// speedup vs baseline: 1.3057x; 1.0020x over previous
#include <cuda_runtime.h>

#define BB 16
#define QN 128
#define KN 512
#define HN 128
#define DD 128
#define QT 8
#define RT 32          // proj row-tile
#define HC 16          // h-chunk size for smem staging

// scratch: g_kpt holds f16x2-packed {kv,kv} per element, same [b][h][k] layout
__device__ float g_kpt[BB * HN * KN];
__device__ float g_qh [BB * QN * HN];

__device__ __forceinline__ float ex2f(float x) {
    float r; asm("ex2.approx.f32 %0, %1;" : "=f"(r) : "f"(x)); return r;
}
__device__ __forceinline__ unsigned pack_h2(float hi, float lo) {
    unsigned r; asm("cvt.rn.f16x2.f32 %0, %1, %2;" : "=r"(r) : "f"(hi), "f"(lo)); return r;
}
__device__ __forceinline__ unsigned hadd2(unsigned a, unsigned b) {
    unsigned r; asm("add.f16x2 %0, %1, %2;" : "=r"(r) : "r"(a), "r"(b)); return r;
}
__device__ __forceinline__ unsigned hfma2(unsigned a, unsigned b, unsigned c) {
    unsigned r; asm("fma.rn.f16x2 %0, %1, %2, %3;" : "=r"(r) : "r"(a), "r"(b), "r"(c)); return r;
}
__device__ __forceinline__ unsigned tanh2(unsigned x) {
    unsigned r; asm("tanh.approx.f16x2 %0, %1;" : "=r"(r) : "r"(x)); return r;
}
__device__ __forceinline__ void unpack_h2(unsigned x, float& lo, float& hi) {
    asm("{\n\t.reg .f16 l, h;\n\tmov.b32 {l, h}, %2;\n\t"
        "cvt.f32.f16 %0, l;\n\tcvt.f32.f16 %1, h;\n\t}"
        : "=f"(lo), "=f"(hi) : "r"(x));
}
__device__ __forceinline__ unsigned smem_u32(const void* p) {
    return (unsigned)__cvta_generic_to_shared(p);
}
__device__ __forceinline__ void cp_async16(unsigned dst, const void* src) {
    asm volatile("cp.async.cg.shared.global [%0], [%1], 16;" :: "r"(dst), "l"(src));
}

// ---------------------------------------------------------------------------
// proj_kernel: smem-tiled GEMM, 32-row tiles. Key path stores f16x2-dup pack.
// ---------------------------------------------------------------------------
__global__ __launch_bounds__(512) void proj_kernel(
    const float* __restrict__ keys, const float* __restrict__ queries,
    const float* __restrict__ Wk,   const float* __restrict__ Wq)
{
    extern __shared__ float dynsmem[];
    float* swt = dynsmem;                                  // [d][h] 128x128
    float (*srt)[36] = (float(*)[36])(dynsmem + DD * HN);  // [d][r] 128x36

    const int b   = blockIdx.y;
    const int tid = threadIdx.x;
    const bool isQ = blockIdx.x >= (KN / RT);
    const int r0  = (isQ ? (blockIdx.x - KN / RT) : blockIdx.x) * RT;
    const float* W    = isQ ? Wq : Wk;
    const float* rows = isQ ? (queries + (size_t)(b * QN + r0) * DD)
                            : (keys    + (size_t)(b * KN + r0) * DD);

    #pragma unroll
    for (int i = 0; i < 32; i++)
        swt[tid + i * 512] = W[tid + i * 512];
    #pragma unroll
    for (int i = 0; i < 8; i++) {
        int idx = tid + i * 512;
        srt[idx & 127][idx >> 7] = rows[idx];
    }
    __syncthreads();

    if (!isQ) {
        const int kt = tid & 3, ht = tid >> 2;
        float acc[8];
        #pragma unroll
        for (int i = 0; i < 8; i++) acc[i] = 0.f;
        #pragma unroll 8
        for (int d = 0; d < DD; d++) {
            const float4* s4 = (const float4*)&srt[d][0];
            float4 ka = s4[kt * 2], kb = s4[kt * 2 + 1];
            float w = swt[d * HN + ht];
            acc[0] = fmaf(ka.x, w, acc[0]);
            acc[1] = fmaf(ka.y, w, acc[1]);
            acc[2] = fmaf(ka.z, w, acc[2]);
            acc[3] = fmaf(ka.w, w, acc[3]);
            acc[4] = fmaf(kb.x, w, acc[4]);
            acc[5] = fmaf(kb.y, w, acc[5]);
            acc[6] = fmaf(kb.z, w, acc[6]);
            acc[7] = fmaf(kb.w, w, acc[7]);
        }
        __syncthreads();
        #pragma unroll
        for (int i = 0; i < 8; i++)
            srt[ht][kt * 8 + i] = __uint_as_float(pack_h2(acc[i], acc[i]));
        __syncthreads();
        #pragma unroll
        for (int i = 0; i < 2; i++) {
            int t = tid + i * 512;
            int h = t >> 3, k4 = t & 7;
            float4 v = *(const float4*)&srt[h][k4 * 4];
            *(float4*)&g_kpt[(size_t)(b * HN + h) * KN + r0 + k4 * 4] = v;
        }
    } else {
        const int qt = tid & 15, ht2 = tid >> 4;
        float acc[2][4];
        #pragma unroll
        for (int j = 0; j < 2; j++)
            #pragma unroll
            for (int i = 0; i < 4; i++) acc[j][i] = 0.f;
        #pragma unroll 8
        for (int d = 0; d < DD; d++) {
            float2 qv = *(const float2*)&srt[d][qt * 2];
            float4 w4 = *(const float4*)&swt[d * HN + ht2 * 4];
            acc[0][0] = fmaf(qv.x, w4.x, acc[0][0]);
            acc[0][1] = fmaf(qv.x, w4.y, acc[0][1]);
            acc[0][2] = fmaf(qv.x, w4.z, acc[0][2]);
            acc[0][3] = fmaf(qv.x, w4.w, acc[0][3]);
            acc[1][0] = fmaf(qv.y, w4.x, acc[1][0]);
            acc[1][1] = fmaf(qv.y, w4.y, acc[1][1]);
            acc[1][2] = fmaf(qv.y, w4.z, acc[1][2]);
            acc[1][3] = fmaf(qv.y, w4.w, acc[1][3]);
        }
        #pragma unroll
        for (int j = 0; j < 2; j++) {
            float* op = &g_qh[(size_t)(b * QN + r0 + qt * 2 + j) * HN + ht2 * 4];
            *(float4*)op = make_float4(acc[j][0], acc[j][1], acc[j][2], acc[j][3]);
        }
    }
}

// ---------------------------------------------------------------------------
// attn_kernel: one block per (b, 8-query tile). 512 threads (thread = key).
// Phase 1: cp.async smem pipeline + all-f16x2 tanh/FMA chain, drain every 8 h.
// ---------------------------------------------------------------------------
__global__ __launch_bounds__(512, 2) void attn_kernel(
    const float* __restrict__ values, const int* __restrict__ valid_lens,
    const float* __restrict__ wv, float* __restrict__ out)
{
    extern __shared__ float dsm[];
    float*    kbuf = dsm;                          // 2*HC*512 = 16384 floats (packed bits)
    float*    sc   = dsm + 2 * HC * 512;           // 4096 floats
    unsigned* sqh2 = (unsigned*)(sc + QT * KN);    // 512 u32
    unsigned* swv2 = sqh2 + HN * 4;                // 128 u32 (packed {w,w})
    float*    redv = (float*)(swv2 + HN);          // 128 (QT x 16)
    float*    smax = redv + QT * 16;               // 8
    float*    sinv = smax + QT;                    // 8
    float*    part = kbuf;                         // alias (phase 2 only)

    const int q0 = blockIdx.x * QT, b = blockIdx.y;
    const int tid = threadIdx.x;
    const float LOG2E = 1.4426950408889634f;

    const int vlen = __ldg(&valid_lens[b]);

    {   // stage q-projection pairs as f16x2
        int h = tid >> 2, p = tid & 3;
        const float* qb = &g_qh[(size_t)(b * QN + q0 + 2 * p) * HN + h];
        float qlo = qb[0], qhi = qb[HN];
        sqh2[h * 4 + p] = pack_h2(qhi, qlo);
    }
    if (tid < HN) {
        float w = wv[tid];
        swv2[tid] = pack_h2(w, w);
    }

    // ---- phase 1: pipelined over 8 chunks of 16 h ----
    const int k = tid;
    const float* kbase = &g_kpt[(size_t)(b * HN) * KN];
    float s[QT];
    #pragma unroll
    for (int q = 0; q < QT; q++) s[q] = 0.f;

    // prefetch chunk 0
    {
        const float4* src = (const float4*)(kbase) + tid;
        unsigned dst = smem_u32(kbuf) + tid * 16;
        #pragma unroll
        for (int i = 0; i < 4; i++)
            cp_async16(dst + i * 512 * 16, src + i * 512);
        asm volatile("cp.async.commit_group;");
    }

    #pragma unroll 1
    for (int c = 0; c < HN / HC; c++) {
        if (c < HN / HC - 1) {
            const float4* src = (const float4*)(kbase + (size_t)(c + 1) * HC * KN) + tid;
            unsigned dst = smem_u32(kbuf + ((c + 1) & 1) * HC * KN) + tid * 16;
            #pragma unroll
            for (int i = 0; i < 4; i++)
                cp_async16(dst + i * 512 * 16, src + i * 512);
            asm volatile("cp.async.commit_group;");
            asm volatile("cp.async.wait_group 1;");
        } else {
            asm volatile("cp.async.wait_group 0;");
        }
        __syncthreads();

        const unsigned* kb2 = (const unsigned*)(kbuf + (c & 1) * HC * KN);
        unsigned acc2[4] = {0u, 0u, 0u, 0u};
        #pragma unroll
        for (int j = 0; j < HC; j++) {
            const int h = c * HC + j;
            const unsigned kv2 = kb2[j * KN + k];
            const unsigned w2  = swv2[h];
            uint4 qp = *(const uint4*)&sqh2[h * 4];
            acc2[0] = hfma2(w2, tanh2(hadd2(kv2, qp.x)), acc2[0]);
            acc2[1] = hfma2(w2, tanh2(hadd2(kv2, qp.y)), acc2[1]);
            acc2[2] = hfma2(w2, tanh2(hadd2(kv2, qp.z)), acc2[2]);
            acc2[3] = hfma2(w2, tanh2(hadd2(kv2, qp.w)), acc2[3]);
            if ((j & 7) == 7) {     // drain every 8 h to f32
                float lo, hi;
                unpack_h2(acc2[0], lo, hi); s[0] += lo; s[1] += hi;
                unpack_h2(acc2[1], lo, hi); s[2] += lo; s[3] += hi;
                unpack_h2(acc2[2], lo, hi); s[4] += lo; s[5] += hi;
                unpack_h2(acc2[3], lo, hi); s[6] += lo; s[7] += hi;
                acc2[0] = acc2[1] = acc2[2] = acc2[3] = 0u;
            }
        }
        __syncthreads();
    }

    if (k >= vlen) {
        #pragma unroll
        for (int q = 0; q < QT; q++) s[q] = -1000000.0f;
    }

    // ---- masked softmax over 512 keys, 8 queries ----
    {
        float mx[QT];
        #pragma unroll
        for (int q = 0; q < QT; q++) mx[q] = s[q];
        #pragma unroll
        for (int off = 16; off; off >>= 1)
            #pragma unroll
            for (int q = 0; q < QT; q++)
                mx[q] = fmaxf(mx[q], __shfl_xor_sync(0xFFFFFFFFu, mx[q], off));
        if ((tid & 31) == 0)
            #pragma unroll
            for (int q = 0; q < QT; q++) redv[q * 16 + (tid >> 5)] = mx[q];
    }
    __syncthreads();
    if (tid < 128) {
        int q = tid >> 4, w = tid & 15;
        float m = redv[q * 16 + w];
        #pragma unroll
        for (int off = 8; off; off >>= 1)
            m = fmaxf(m, __shfl_xor_sync(0xFFFFFFFFu, m, off));
        if (w == 0) smax[q] = m;
    }
    __syncthreads();

    float p[QT];
    {
        float sm[QT];
        #pragma unroll
        for (int q = 0; q < QT; q++) {
            p[q] = ex2f((s[q] - smax[q]) * LOG2E);
            sm[q] = p[q];
        }
        #pragma unroll
        for (int off = 16; off; off >>= 1)
            #pragma unroll
            for (int q = 0; q < QT; q++)
                sm[q] += __shfl_xor_sync(0xFFFFFFFFu, sm[q], off);
        if ((tid & 31) == 0)
            #pragma unroll
            for (int q = 0; q < QT; q++) redv[q * 16 + (tid >> 5)] = sm[q];
    }
    __syncthreads();
    if (tid < 128) {
        int q = tid >> 4, w = tid & 15;
        float t = redv[q * 16 + w];
        #pragma unroll
        for (int off = 8; off; off >>= 1)
            t += __shfl_xor_sync(0xFFFFFFFFu, t, off);
        if (w == 0) sinv[q] = 1.0f / t;
    }
    __syncthreads();
    #pragma unroll
    for (int q = 0; q < QT; q++) sc[q * KN + k] = p[q] * sinv[q];
    __syncthreads();

    // ---- phase 2: out = attn @ values. 8 value loads batched per group ----
    {
        const int v = tid & 127, g = tid >> 7;
        const float* vp = values + (size_t)(b * KN + g * 128) * DD + v;
        float a[QT];
        #pragma unroll
        for (int q = 0; q < QT; q++) a[q] = 0.f;

        #pragma unroll 1
        for (int kk = 0; kk < 128; kk += 8) {
            float vv[8];
            #pragma unroll
            for (int j = 0; j < 8; j++)
                vv[j] = vp[(size_t)(kk + j) * DD];
            const int ki = g * 128 + kk;
            #pragma unroll
            for (int q = 0; q < QT; q++) {
                float4 c0 = *(const float4*)&sc[q * KN + ki];
                float4 c1 = *(const float4*)&sc[q * KN + ki + 4];
                a[q] = fmaf(c0.x, vv[0], a[q]);
                a[q] = fmaf(c0.y, vv[1], a[q]);
                a[q] = fmaf(c0.z, vv[2], a[q]);
                a[q] = fmaf(c0.w, vv[3], a[q]);
                a[q] = fmaf(c1.x, vv[4], a[q]);
                a[q] = fmaf(c1.y, vv[5], a[q]);
                a[q] = fmaf(c1.z, vv[6], a[q]);
                a[q] = fmaf(c1.w, vv[7], a[q]);
            }
        }
        #pragma unroll
        for (int q = 0; q < QT; q++) part[q * 512 + tid] = a[q];
    }
    __syncthreads();
    #pragma unroll
    for (int i = 0; i < 2; i++) {
        int t = tid + i * 512;
        int q = t >> 7, v = t & 127;
        const float* pq = &part[q * 512];
        out[(size_t)(b * QN + q0 + q) * DD + v] =
            (pq[v] + pq[128 + v]) + (pq[256 + v] + pq[384 + v]);
    }
}

extern "C" void kernel_launch(void* const* d_in, const int* in_sizes, int n_in,
                              void* d_out, int out_size)
{
    const float* queries = (const float*)d_in[0];
    const float* keys    = (const float*)d_in[1];
    const float* values  = (const float*)d_in[2];
    const int*   vlens   = (const int*)  d_in[3];
    const float* Wq      = (const float*)d_in[4];
    const float* Wk      = (const float*)d_in[5];
    const float* wv      = (const float*)d_in[6];
    float* out = (float*)d_out;

    const int proj_smem = (DD * HN + DD * 36) * sizeof(float);   // 83,968 B
    cudaFuncSetAttribute(proj_kernel,
                         cudaFuncAttributeMaxDynamicSharedMemorySize, proj_smem);

    const int attn_smem = (2 * HC * 512 + QT * KN + 512 + HN + QT * 16 + 2 * QT + 32)
                          * sizeof(float);                        // ~84 KB
    cudaFuncSetAttribute(attn_kernel,
                         cudaFuncAttributeMaxDynamicSharedMemorySize, attn_smem);

    proj_kernel<<<dim3(KN / RT + QN / RT, BB), 512, proj_smem>>>(keys, queries, Wk, Wq);
    attn_kernel<<<dim3(QN / QT, BB), 512, attn_smem>>>(values, vlens, wv, out);
}

// round 12
// speedup vs baseline: 1.4459x; 1.1074x over previous
#include <cuda_runtime.h>

#define BB 16
#define QN 128
#define KN 512
#define HN 128
#define DD 128
#define QT 8
#define RT 32          // proj row-tile

// scratch: g_kpt holds f16x2-packed {kv,kv} per element, layout [b][h][k]
__device__ float g_kpt[BB * HN * KN];
__device__ float g_qh [BB * QN * HN];

__device__ __forceinline__ float ex2f(float x) {
    float r; asm("ex2.approx.f32 %0, %1;" : "=f"(r) : "f"(x)); return r;
}
__device__ __forceinline__ unsigned pack_h2(float hi, float lo) {
    unsigned r; asm("cvt.rn.f16x2.f32 %0, %1, %2;" : "=r"(r) : "f"(hi), "f"(lo)); return r;
}
__device__ __forceinline__ unsigned hadd2(unsigned a, unsigned b) {
    unsigned r; asm("add.f16x2 %0, %1, %2;" : "=r"(r) : "r"(a), "r"(b)); return r;
}
__device__ __forceinline__ unsigned hfma2(unsigned a, unsigned b, unsigned c) {
    unsigned r; asm("fma.rn.f16x2 %0, %1, %2, %3;" : "=r"(r) : "r"(a), "r"(b), "r"(c)); return r;
}
__device__ __forceinline__ unsigned tanh2(unsigned x) {
    unsigned r; asm("tanh.approx.f16x2 %0, %1;" : "=r"(r) : "r"(x)); return r;
}
__device__ __forceinline__ void unpack_h2(unsigned x, float& lo, float& hi) {
    asm("{\n\t.reg .f16 l, h;\n\tmov.b32 {l, h}, %2;\n\t"
        "cvt.f32.f16 %0, l;\n\tcvt.f32.f16 %1, h;\n\t}"
        : "=f"(lo), "=f"(hi) : "r"(x));
}

// ---------------------------------------------------------------------------
// proj_kernel: rows staged in smem (18KB); W read from L2 with coalesced
// batched LDGs. Key path packs f16x2 before the transposed store.
// ---------------------------------------------------------------------------
__global__ __launch_bounds__(512) void proj_kernel(
    const float* __restrict__ keys, const float* __restrict__ queries,
    const float* __restrict__ Wk,   const float* __restrict__ Wq)
{
    __shared__ float srt[DD][36];       // [d][r], 32 rows used

    const int b   = blockIdx.y;
    const int tid = threadIdx.x;
    const bool isQ = blockIdx.x >= (KN / RT);
    const int r0  = (isQ ? (blockIdx.x - KN / RT) : blockIdx.x) * RT;
    const float* W    = isQ ? Wq : Wk;
    const float* rows = isQ ? (queries + (size_t)(b * QN + r0) * DD)
                            : (keys    + (size_t)(b * KN + r0) * DD);

    #pragma unroll
    for (int i = 0; i < 8; i++) {                  // 32 rows x 128 d
        int idx = tid + i * 512;
        srt[idx & 127][idx >> 7] = rows[idx];
    }
    __syncthreads();

    if (!isQ) {
        // thread = (kt = tid>>7 in 0..3 : 8-key group, ht = tid&127 : one h)
        // W reads coalesced (consecutive ht), srt reads warp-broadcast.
        const int kt = tid >> 7, ht = tid & 127;
        float acc[8];
        #pragma unroll
        for (int i = 0; i < 8; i++) acc[i] = 0.f;
        #pragma unroll 1
        for (int db = 0; db < DD; db += 8) {
            float wb[8];
            #pragma unroll
            for (int j = 0; j < 8; j++)
                wb[j] = W[(db + j) * HN + ht];
            #pragma unroll
            for (int j = 0; j < 8; j++) {
                const float4* s4 = (const float4*)&srt[db + j][0];
                float4 ka = s4[kt * 2], kb = s4[kt * 2 + 1];
                float w = wb[j];
                acc[0] = fmaf(ka.x, w, acc[0]);
                acc[1] = fmaf(ka.y, w, acc[1]);
                acc[2] = fmaf(ka.z, w, acc[2]);
                acc[3] = fmaf(ka.w, w, acc[3]);
                acc[4] = fmaf(kb.x, w, acc[4]);
                acc[5] = fmaf(kb.y, w, acc[5]);
                acc[6] = fmaf(kb.z, w, acc[6]);
                acc[7] = fmaf(kb.w, w, acc[7]);
            }
        }
        __syncthreads();
        #pragma unroll
        for (int i = 0; i < 8; i++)
            srt[ht][kt * 8 + i] = __uint_as_float(pack_h2(acc[i], acc[i]));
        __syncthreads();
        #pragma unroll
        for (int i = 0; i < 2; i++) {
            int t = tid + i * 512;                 // 1024 float4
            int h = t >> 3, k4 = t & 7;
            float4 v = *(const float4*)&srt[h][k4 * 4];
            *(float4*)&g_kpt[(size_t)(b * HN + h) * KN + r0 + k4 * 4] = v;
        }
    } else {
        // thread = (qt = tid>>5 in 0..15 : 2 queries, ht2 = tid&31 : 4 h)
        // W float4 reads coalesced across warp; srt float2 warp-broadcast.
        const int qt = tid >> 5, ht2 = tid & 31;
        float acc[2][4];
        #pragma unroll
        for (int j = 0; j < 2; j++)
            #pragma unroll
            for (int i = 0; i < 4; i++) acc[j][i] = 0.f;
        #pragma unroll 1
        for (int db = 0; db < DD; db += 4) {
            float4 w4[4];
            #pragma unroll
            for (int j = 0; j < 4; j++)
                w4[j] = *(const float4*)&W[(db + j) * HN + ht2 * 4];
            #pragma unroll
            for (int j = 0; j < 4; j++) {
                float2 qv = *(const float2*)&srt[db + j][qt * 2];
                acc[0][0] = fmaf(qv.x, w4[j].x, acc[0][0]);
                acc[0][1] = fmaf(qv.x, w4[j].y, acc[0][1]);
                acc[0][2] = fmaf(qv.x, w4[j].z, acc[0][2]);
                acc[0][3] = fmaf(qv.x, w4[j].w, acc[0][3]);
                acc[1][0] = fmaf(qv.y, w4[j].x, acc[1][0]);
                acc[1][1] = fmaf(qv.y, w4[j].y, acc[1][1]);
                acc[1][2] = fmaf(qv.y, w4[j].z, acc[1][2]);
                acc[1][3] = fmaf(qv.y, w4[j].w, acc[1][3]);
            }
        }
        #pragma unroll
        for (int j = 0; j < 2; j++) {
            float* op = &g_qh[(size_t)(b * QN + r0 + qt * 2 + j) * HN + ht2 * 4];
            *(float4*)op = make_float4(acc[j][0], acc[j][1], acc[j][2], acc[j][3]);
        }
    }
}

// ---------------------------------------------------------------------------
// attn_kernel: one block per (b, 8-query tile). 512 threads (thread = key).
// Packed f16x2 math; direct LDG (batch 4); launch_bounds(512,3) for 48 w/SM.
// ---------------------------------------------------------------------------
__global__ __launch_bounds__(512, 3) void attn_kernel(
    const float* __restrict__ values, const int* __restrict__ valid_lens,
    const float* __restrict__ wv, float* __restrict__ out)
{
    __shared__ float    sc[QT * KN];     // 16KB attn weights
    __shared__ float    part[QT * 512];  // 16KB split-K partials
    __shared__ unsigned sqh2[HN * 4];    // 2KB packed q-proj pairs
    __shared__ unsigned swv2[HN];        // packed {w,w}
    __shared__ float    redv[QT * 16];
    __shared__ float    smax[QT], sinv[QT];

    const int q0 = blockIdx.x * QT, b = blockIdx.y;
    const int tid = threadIdx.x;
    const float LOG2E = 1.4426950408889634f;

    const int vlen = __ldg(&valid_lens[b]);

    {   // stage q-projection pairs as f16x2
        int h = tid >> 2, p = tid & 3;
        const float* qb = &g_qh[(size_t)(b * QN + q0 + 2 * p) * HN + h];
        float qlo = qb[0], qhi = qb[HN];
        sqh2[h * 4 + p] = pack_h2(qhi, qlo);
    }
    if (tid < HN) {
        float w = wv[tid];
        swv2[tid] = pack_h2(w, w);
    }
    __syncthreads();

    // ---- phase 1: scores, packed math, kv batch of 4 ----
    const int k = tid;
    const unsigned* kp = (const unsigned*)&g_kpt[(size_t)(b * HN) * KN + k];
    float s[QT];
    #pragma unroll
    for (int q = 0; q < QT; q++) s[q] = 0.f;

    unsigned acc2[4] = {0u, 0u, 0u, 0u};
    #pragma unroll 1
    for (int hb = 0; hb < HN; hb += 8) {
        #pragma unroll
        for (int half = 0; half < 2; half++) {
            unsigned kv2[4];
            #pragma unroll
            for (int j = 0; j < 4; j++)
                kv2[j] = kp[(size_t)(hb + half * 4 + j) * KN];
            #pragma unroll
            for (int j = 0; j < 4; j++) {
                const int h = hb + half * 4 + j;
                const unsigned w2 = swv2[h];
                uint4 qp = *(const uint4*)&sqh2[h * 4];
                acc2[0] = hfma2(w2, tanh2(hadd2(kv2[j], qp.x)), acc2[0]);
                acc2[1] = hfma2(w2, tanh2(hadd2(kv2[j], qp.y)), acc2[1]);
                acc2[2] = hfma2(w2, tanh2(hadd2(kv2[j], qp.z)), acc2[2]);
                acc2[3] = hfma2(w2, tanh2(hadd2(kv2[j], qp.w)), acc2[3]);
            }
        }
        {   // drain every 8 h to f32
            float lo, hi;
            unpack_h2(acc2[0], lo, hi); s[0] += lo; s[1] += hi;
            unpack_h2(acc2[1], lo, hi); s[2] += lo; s[3] += hi;
            unpack_h2(acc2[2], lo, hi); s[4] += lo; s[5] += hi;
            unpack_h2(acc2[3], lo, hi); s[6] += lo; s[7] += hi;
            acc2[0] = acc2[1] = acc2[2] = acc2[3] = 0u;
        }
    }

    if (k >= vlen) {
        #pragma unroll
        for (int q = 0; q < QT; q++) s[q] = -1000000.0f;
    }

    // ---- masked softmax over 512 keys, 8 queries ----
    {
        float mx[QT];
        #pragma unroll
        for (int q = 0; q < QT; q++) mx[q] = s[q];
        #pragma unroll
        for (int off = 16; off; off >>= 1)
            #pragma unroll
            for (int q = 0; q < QT; q++)
                mx[q] = fmaxf(mx[q], __shfl_xor_sync(0xFFFFFFFFu, mx[q], off));
        if ((tid & 31) == 0)
            #pragma unroll
            for (int q = 0; q < QT; q++) redv[q * 16 + (tid >> 5)] = mx[q];
    }
    __syncthreads();
    if (tid < 128) {
        int q = tid >> 4, w = tid & 15;
        float m = redv[q * 16 + w];
        #pragma unroll
        for (int off = 8; off; off >>= 1)
            m = fmaxf(m, __shfl_xor_sync(0xFFFFFFFFu, m, off));
        if (w == 0) smax[q] = m;
    }
    __syncthreads();

    float p[QT];
    {
        float sm[QT];
        #pragma unroll
        for (int q = 0; q < QT; q++) {
            p[q] = ex2f((s[q] - smax[q]) * LOG2E);
            sm[q] = p[q];
        }
        #pragma unroll
        for (int off = 16; off; off >>= 1)
            #pragma unroll
            for (int q = 0; q < QT; q++)
                sm[q] += __shfl_xor_sync(0xFFFFFFFFu, sm[q], off);
        if ((tid & 31) == 0)
            #pragma unroll
            for (int q = 0; q < QT; q++) redv[q * 16 + (tid >> 5)] = sm[q];
    }
    __syncthreads();
    if (tid < 128) {
        int q = tid >> 4, w = tid & 15;
        float t = redv[q * 16 + w];
        #pragma unroll
        for (int off = 8; off; off >>= 1)
            t += __shfl_xor_sync(0xFFFFFFFFu, t, off);
        if (w == 0) sinv[q] = 1.0f / t;
    }
    __syncthreads();
    #pragma unroll
    for (int q = 0; q < QT; q++) sc[q * KN + k] = p[q] * sinv[q];
    __syncthreads();

    // ---- phase 2: out = attn @ values. 8 value loads batched per group ----
    {
        const int v = tid & 127, g = tid >> 7;
        const float* vp = values + (size_t)(b * KN + g * 128) * DD + v;
        float a[QT];
        #pragma unroll
        for (int q = 0; q < QT; q++) a[q] = 0.f;

        #pragma unroll 1
        for (int kk = 0; kk < 128; kk += 8) {
            float vv[8];
            #pragma unroll
            for (int j = 0; j < 8; j++)
                vv[j] = vp[(size_t)(kk + j) * DD];
            const int ki = g * 128 + kk;
            #pragma unroll
            for (int q = 0; q < QT; q++) {
                float4 c0 = *(const float4*)&sc[q * KN + ki];
                float4 c1 = *(const float4*)&sc[q * KN + ki + 4];
                a[q] = fmaf(c0.x, vv[0], a[q]);
                a[q] = fmaf(c0.y, vv[1], a[q]);
                a[q] = fmaf(c0.z, vv[2], a[q]);
                a[q] = fmaf(c0.w, vv[3], a[q]);
                a[q] = fmaf(c1.x, vv[4], a[q]);
                a[q] = fmaf(c1.y, vv[5], a[q]);
                a[q] = fmaf(c1.z, vv[6], a[q]);
                a[q] = fmaf(c1.w, vv[7], a[q]);
            }
        }
        #pragma unroll
        for (int q = 0; q < QT; q++) part[q * 512 + tid] = a[q];
    }
    __syncthreads();
    #pragma unroll
    for (int i = 0; i < 2; i++) {
        int t = tid + i * 512;
        int q = t >> 7, v = t & 127;
        const float* pq = &part[q * 512];
        out[(size_t)(b * QN + q0 + q) * DD + v] =
            (pq[v] + pq[128 + v]) + (pq[256 + v] + pq[384 + v]);
    }
}

extern "C" void kernel_launch(void* const* d_in, const int* in_sizes, int n_in,
                              void* d_out, int out_size)
{
    const float* queries = (const float*)d_in[0];
    const float* keys    = (const float*)d_in[1];
    const float* values  = (const float*)d_in[2];
    const int*   vlens   = (const int*)  d_in[3];
    const float* Wq      = (const float*)d_in[4];
    const float* Wk      = (const float*)d_in[5];
    const float* wv      = (const float*)d_in[6];
    float* out = (float*)d_out;

    proj_kernel<<<dim3(KN / RT + QN / RT, BB), 512>>>(keys, queries, Wk, Wq);
    attn_kernel<<<dim3(QN / QT, BB), 512>>>(values, vlens, wv, out);
}

// round 13
// speedup vs baseline: 1.6901x; 1.1689x over previous
#include <cuda_runtime.h>

#define BB 16
#define QN 128
#define KN 512
#define HN 128
#define DD 128
#define QT 8
#define RT 32          // proj row-tile

// scratch: g_kpt holds f16x2-packed {kv,kv} per element, layout [b][h][k]
__device__ float g_kpt[BB * HN * KN];
__device__ float g_qh [BB * QN * HN];

__device__ __forceinline__ float ex2f(float x) {
    float r; asm("ex2.approx.f32 %0, %1;" : "=f"(r) : "f"(x)); return r;
}
__device__ __forceinline__ unsigned pack_h2(float hi, float lo) {
    unsigned r; asm("cvt.rn.f16x2.f32 %0, %1, %2;" : "=r"(r) : "f"(hi), "f"(lo)); return r;
}
__device__ __forceinline__ unsigned hadd2(unsigned a, unsigned b) {
    unsigned r; asm("add.f16x2 %0, %1, %2;" : "=r"(r) : "r"(a), "r"(b)); return r;
}
__device__ __forceinline__ unsigned hfma2(unsigned a, unsigned b, unsigned c) {
    unsigned r; asm("fma.rn.f16x2 %0, %1, %2, %3;" : "=r"(r) : "r"(a), "r"(b), "r"(c)); return r;
}
__device__ __forceinline__ unsigned tanh2(unsigned x) {
    unsigned r; asm("tanh.approx.f16x2 %0, %1;" : "=r"(r) : "r"(x)); return r;
}
__device__ __forceinline__ void unpack_h2(unsigned x, float& lo, float& hi) {
    asm("{\n\t.reg .f16 l, h;\n\tmov.b32 {l, h}, %2;\n\t"
        "cvt.f32.f16 %0, l;\n\tcvt.f32.f16 %1, h;\n\t}"
        : "=f"(lo), "=f"(hi) : "r"(x));
}

// ---------------------------------------------------------------------------
// proj_kernel: rows staged in smem (18KB); W read from L2 with coalesced
// batched LDGs. Key path packs f16x2 before the transposed store. (R12)
// ---------------------------------------------------------------------------
__global__ __launch_bounds__(512) void proj_kernel(
    const float* __restrict__ keys, const float* __restrict__ queries,
    const float* __restrict__ Wk,   const float* __restrict__ Wq)
{
    __shared__ float srt[DD][36];       // [d][r], 32 rows used

    const int b   = blockIdx.y;
    const int tid = threadIdx.x;
    const bool isQ = blockIdx.x >= (KN / RT);
    const int r0  = (isQ ? (blockIdx.x - KN / RT) : blockIdx.x) * RT;
    const float* W    = isQ ? Wq : Wk;
    const float* rows = isQ ? (queries + (size_t)(b * QN + r0) * DD)
                            : (keys    + (size_t)(b * KN + r0) * DD);

    #pragma unroll
    for (int i = 0; i < 8; i++) {
        int idx = tid + i * 512;
        srt[idx & 127][idx >> 7] = rows[idx];
    }
    __syncthreads();

    if (!isQ) {
        const int kt = tid >> 7, ht = tid & 127;
        float acc[8];
        #pragma unroll
        for (int i = 0; i < 8; i++) acc[i] = 0.f;
        #pragma unroll 1
        for (int db = 0; db < DD; db += 8) {
            float wb[8];
            #pragma unroll
            for (int j = 0; j < 8; j++)
                wb[j] = W[(db + j) * HN + ht];
            #pragma unroll
            for (int j = 0; j < 8; j++) {
                const float4* s4 = (const float4*)&srt[db + j][0];
                float4 ka = s4[kt * 2], kb = s4[kt * 2 + 1];
                float w = wb[j];
                acc[0] = fmaf(ka.x, w, acc[0]);
                acc[1] = fmaf(ka.y, w, acc[1]);
                acc[2] = fmaf(ka.z, w, acc[2]);
                acc[3] = fmaf(ka.w, w, acc[3]);
                acc[4] = fmaf(kb.x, w, acc[4]);
                acc[5] = fmaf(kb.y, w, acc[5]);
                acc[6] = fmaf(kb.z, w, acc[6]);
                acc[7] = fmaf(kb.w, w, acc[7]);
            }
        }
        __syncthreads();
        #pragma unroll
        for (int i = 0; i < 8; i++)
            srt[ht][kt * 8 + i] = __uint_as_float(pack_h2(acc[i], acc[i]));
        __syncthreads();
        #pragma unroll
        for (int i = 0; i < 2; i++) {
            int t = tid + i * 512;
            int h = t >> 3, k4 = t & 7;
            float4 v = *(const float4*)&srt[h][k4 * 4];
            *(float4*)&g_kpt[(size_t)(b * HN + h) * KN + r0 + k4 * 4] = v;
        }
    } else {
        const int qt = tid >> 5, ht2 = tid & 31;
        float acc[2][4];
        #pragma unroll
        for (int j = 0; j < 2; j++)
            #pragma unroll
            for (int i = 0; i < 4; i++) acc[j][i] = 0.f;
        #pragma unroll 1
        for (int db = 0; db < DD; db += 4) {
            float4 w4[4];
            #pragma unroll
            for (int j = 0; j < 4; j++)
                w4[j] = *(const float4*)&W[(db + j) * HN + ht2 * 4];
            #pragma unroll
            for (int j = 0; j < 4; j++) {
                float2 qv = *(const float2*)&srt[db + j][qt * 2];
                acc[0][0] = fmaf(qv.x, w4[j].x, acc[0][0]);
                acc[0][1] = fmaf(qv.x, w4[j].y, acc[0][1]);
                acc[0][2] = fmaf(qv.x, w4[j].z, acc[0][2]);
                acc[0][3] = fmaf(qv.x, w4[j].w, acc[0][3]);
                acc[1][0] = fmaf(qv.y, w4[j].x, acc[1][0]);
                acc[1][1] = fmaf(qv.y, w4[j].y, acc[1][1]);
                acc[1][2] = fmaf(qv.y, w4[j].z, acc[1][2]);
                acc[1][3] = fmaf(qv.y, w4[j].w, acc[1][3]);
            }
        }
        #pragma unroll
        for (int j = 0; j < 2; j++) {
            float* op = &g_qh[(size_t)(b * QN + r0 + qt * 2 + j) * HN + ht2 * 4];
            *(float4*)op = make_float4(acc[j][0], acc[j][1], acc[j][2], acc[j][3]);
        }
    }
}

// ---------------------------------------------------------------------------
// attn_kernel: one block per (b, 8-query tile). 512 threads (thread = key).
// Masked keys (k >= vlen) skip ALL phase-1 tanh work and phase-2 groups
// beyond vlen skip their FMA loops (sc there is exactly 0).
// ---------------------------------------------------------------------------
__global__ __launch_bounds__(512, 2) void attn_kernel(
    const float* __restrict__ values, const int* __restrict__ valid_lens,
    const float* __restrict__ wv, float* __restrict__ out)
{
    __shared__ float    sc[QT * KN];     // 16KB attn weights
    __shared__ float    part[QT * 512];  // 16KB split-K partials
    __shared__ unsigned sqh2[HN * 4];    // 2KB packed q-proj pairs
    __shared__ unsigned swv2[HN];        // packed {w,w}
    __shared__ float    redv[QT * 16];
    __shared__ float    smax[QT], sinv[QT];

    const int q0 = blockIdx.x * QT, b = blockIdx.y;
    const int tid = threadIdx.x;
    const float LOG2E = 1.4426950408889634f;

    const int vlen = __ldg(&valid_lens[b]);

    {   // stage q-projection pairs as f16x2
        int h = tid >> 2, p = tid & 3;
        const float* qb = &g_qh[(size_t)(b * QN + q0 + 2 * p) * HN + h];
        float qlo = qb[0], qhi = qb[HN];
        sqh2[h * 4 + p] = pack_h2(qhi, qlo);
    }
    if (tid < HN) {
        float w = wv[tid];
        swv2[tid] = pack_h2(w, w);
    }
    __syncthreads();

    // ---- phase 1: scores. Only valid keys compute; kv batch 8 ----
    const int k = tid;
    const unsigned* kp = (const unsigned*)&g_kpt[(size_t)(b * HN) * KN + k];
    const bool active = (k < vlen);
    const int hmax = active ? HN : 0;
    float s[QT];
    #pragma unroll
    for (int q = 0; q < QT; q++) s[q] = 0.f;

    #pragma unroll 1
    for (int hb = 0; hb < hmax; hb += 8) {
        unsigned kv2[8];
        #pragma unroll
        for (int j = 0; j < 8; j++)
            kv2[j] = kp[(size_t)(hb + j) * KN];
        unsigned acc2[4] = {0u, 0u, 0u, 0u};
        #pragma unroll
        for (int j = 0; j < 8; j++) {
            const int h = hb + j;
            const unsigned w2 = swv2[h];
            uint4 qp = *(const uint4*)&sqh2[h * 4];
            acc2[0] = hfma2(w2, tanh2(hadd2(kv2[j], qp.x)), acc2[0]);
            acc2[1] = hfma2(w2, tanh2(hadd2(kv2[j], qp.y)), acc2[1]);
            acc2[2] = hfma2(w2, tanh2(hadd2(kv2[j], qp.z)), acc2[2]);
            acc2[3] = hfma2(w2, tanh2(hadd2(kv2[j], qp.w)), acc2[3]);
        }
        float lo, hi;
        unpack_h2(acc2[0], lo, hi); s[0] += lo; s[1] += hi;
        unpack_h2(acc2[1], lo, hi); s[2] += lo; s[3] += hi;
        unpack_h2(acc2[2], lo, hi); s[4] += lo; s[5] += hi;
        unpack_h2(acc2[3], lo, hi); s[6] += lo; s[7] += hi;
    }

    if (!active) {
        #pragma unroll
        for (int q = 0; q < QT; q++) s[q] = -1000000.0f;
    }

    // ---- masked softmax over 512 keys, 8 queries ----
    {
        float mx[QT];
        #pragma unroll
        for (int q = 0; q < QT; q++) mx[q] = s[q];
        #pragma unroll
        for (int off = 16; off; off >>= 1)
            #pragma unroll
            for (int q = 0; q < QT; q++)
                mx[q] = fmaxf(mx[q], __shfl_xor_sync(0xFFFFFFFFu, mx[q], off));
        if ((tid & 31) == 0)
            #pragma unroll
            for (int q = 0; q < QT; q++) redv[q * 16 + (tid >> 5)] = mx[q];
    }
    __syncthreads();
    if (tid < 128) {
        int q = tid >> 4, w = tid & 15;
        float m = redv[q * 16 + w];
        #pragma unroll
        for (int off = 8; off; off >>= 1)
            m = fmaxf(m, __shfl_xor_sync(0xFFFFFFFFu, m, off));
        if (w == 0) smax[q] = m;
    }
    __syncthreads();

    float p[QT];
    {
        float sm[QT];
        #pragma unroll
        for (int q = 0; q < QT; q++) {
            p[q] = ex2f((s[q] - smax[q]) * LOG2E);
            sm[q] = p[q];
        }
        #pragma unroll
        for (int off = 16; off; off >>= 1)
            #pragma unroll
            for (int q = 0; q < QT; q++)
                sm[q] += __shfl_xor_sync(0xFFFFFFFFu, sm[q], off);
        if ((tid & 31) == 0)
            #pragma unroll
            for (int q = 0; q < QT; q++) redv[q * 16 + (tid >> 5)] = sm[q];
    }
    __syncthreads();
    if (tid < 128) {
        int q = tid >> 4, w = tid & 15;
        float t = redv[q * 16 + w];
        #pragma unroll
        for (int off = 8; off; off >>= 1)
            t += __shfl_xor_sync(0xFFFFFFFFu, t, off);
        if (w == 0) sinv[q] = 1.0f / t;
    }
    __syncthreads();
    #pragma unroll
    for (int q = 0; q < QT; q++) sc[q * KN + k] = p[q] * sinv[q];
    __syncthreads();

    // ---- phase 2: out = attn @ values. Skip key-groups beyond vlen ----
    {
        const int v = tid & 127, g = tid >> 7;
        const float* vp = values + (size_t)(b * KN + g * 128) * DD + v;
        float a[QT];
        #pragma unroll
        for (int q = 0; q < QT; q++) a[q] = 0.f;

        // keys in [g*128, g*128+kklim) can have nonzero sc; beyond, sc == 0.
        int rem = vlen - g * 128;
        int kklim = rem >= 128 ? 128 : (rem > 0 ? ((rem + 7) & ~7) : 0);

        #pragma unroll 1
        for (int kk = 0; kk < kklim; kk += 8) {
            float vv[8];
            #pragma unroll
            for (int j = 0; j < 8; j++)
                vv[j] = vp[(size_t)(kk + j) * DD];
            const int ki = g * 128 + kk;
            #pragma unroll
            for (int q = 0; q < QT; q++) {
                float4 c0 = *(const float4*)&sc[q * KN + ki];
                float4 c1 = *(const float4*)&sc[q * KN + ki + 4];
                a[q] = fmaf(c0.x, vv[0], a[q]);
                a[q] = fmaf(c0.y, vv[1], a[q]);
                a[q] = fmaf(c0.z, vv[2], a[q]);
                a[q] = fmaf(c0.w, vv[3], a[q]);
                a[q] = fmaf(c1.x, vv[4], a[q]);
                a[q] = fmaf(c1.y, vv[5], a[q]);
                a[q] = fmaf(c1.z, vv[6], a[q]);
                a[q] = fmaf(c1.w, vv[7], a[q]);
            }
        }
        #pragma unroll
        for (int q = 0; q < QT; q++) part[q * 512 + tid] = a[q];
    }
    __syncthreads();
    #pragma unroll
    for (int i = 0; i < 2; i++) {
        int t = tid + i * 512;
        int q = t >> 7, v = t & 127;
        const float* pq = &part[q * 512];
        out[(size_t)(b * QN + q0 + q) * DD + v] =
            (pq[v] + pq[128 + v]) + (pq[256 + v] + pq[384 + v]);
    }
}

extern "C" void kernel_launch(void* const* d_in, const int* in_sizes, int n_in,
                              void* d_out, int out_size)
{
    const float* queries = (const float*)d_in[0];
    const float* keys    = (const float*)d_in[1];
    const float* values  = (const float*)d_in[2];
    const int*   vlens   = (const int*)  d_in[3];
    const float* Wq      = (const float*)d_in[4];
    const float* Wk      = (const float*)d_in[5];
    const float* wv      = (const float*)d_in[6];
    float* out = (float*)d_out;

    proj_kernel<<<dim3(KN / RT + QN / RT, BB), 512>>>(keys, queries, Wk, Wq);
    attn_kernel<<<dim3(QN / QT, BB), 512>>>(values, vlens, wv, out);
}

// round 14
// speedup vs baseline: 1.8761x; 1.1101x over previous
#include <cuda_runtime.h>

#define BB 16
#define QN 128
#define KN 512
#define HN 128
#define DD 128
#define QT 8
#define RT 32          // proj row-tile

// scratch: g_kpt holds f16x2-packed {kv,kv} per element, layout [b][h][k]
__device__ float g_kpt[BB * HN * KN];
__device__ float g_qh [BB * QN * HN];
__device__ int   g_perm[(QN / QT) * BB];   // block id -> work item (b*16 + qtile)

__device__ __forceinline__ float ex2f(float x) {
    float r; asm("ex2.approx.f32 %0, %1;" : "=f"(r) : "f"(x)); return r;
}
__device__ __forceinline__ unsigned pack_h2(float hi, float lo) {
    unsigned r; asm("cvt.rn.f16x2.f32 %0, %1, %2;" : "=r"(r) : "f"(hi), "f"(lo)); return r;
}
__device__ __forceinline__ unsigned hadd2(unsigned a, unsigned b) {
    unsigned r; asm("add.f16x2 %0, %1, %2;" : "=r"(r) : "r"(a), "r"(b)); return r;
}
__device__ __forceinline__ unsigned hfma2(unsigned a, unsigned b, unsigned c) {
    unsigned r; asm("fma.rn.f16x2 %0, %1, %2, %3;" : "=r"(r) : "r"(a), "r"(b), "r"(c)); return r;
}
__device__ __forceinline__ unsigned tanh2(unsigned x) {
    unsigned r; asm("tanh.approx.f16x2 %0, %1;" : "=r"(r) : "r"(x)); return r;
}
__device__ __forceinline__ void unpack_h2(unsigned x, float& lo, float& hi) {
    asm("{\n\t.reg .f16 l, h;\n\tmov.b32 {l, h}, %2;\n\t"
        "cvt.f32.f16 %0, l;\n\tcvt.f32.f16 %1, h;\n\t}"
        : "=f"(lo), "=f"(hi) : "r"(x));
}

// ---------------------------------------------------------------------------
// sched_kernel: build a load-balanced bid -> (b, qtile) permutation.
// Classic placement maps bid and bid+148 to the same SM, so pair rank s with
// rank 255-s (heaviest with lightest); singles (bid 108..147) take the middle.
// ---------------------------------------------------------------------------
__global__ void sched_kernel(const int* __restrict__ vlens)
{
    if (threadIdx.x != 0) return;
    int v[BB], order[BB];
    #pragma unroll
    for (int b = 0; b < BB; b++) v[b] = vlens[b];
    #pragma unroll
    for (int b = 0; b < BB; b++) {
        int r = 0;
        #pragma unroll
        for (int j = 0; j < BB; j++)
            if (v[j] > v[b] || (v[j] == v[b] && j < b)) r++;
        order[r] = b;
    }
    // work item at sorted position p: batch order[p>>4], qtile p&15
    #define ITEM(p) (order[(p) >> 4] * 16 + ((p) & 15))
    for (int bid = 0; bid < 108; bid++) {
        g_perm[bid]       = ITEM(bid);
        g_perm[bid + 148] = ITEM(255 - bid);
    }
    for (int bid = 108; bid < 148; bid++)
        g_perm[bid] = ITEM(bid);
    #undef ITEM
}

// ---------------------------------------------------------------------------
// proj_kernel: rows staged in smem; W from L2 with coalesced batched LDGs.
// Key path packs f16x2 before the transposed store. (unchanged from R12)
// ---------------------------------------------------------------------------
__global__ __launch_bounds__(512) void proj_kernel(
    const float* __restrict__ keys, const float* __restrict__ queries,
    const float* __restrict__ Wk,   const float* __restrict__ Wq)
{
    __shared__ float srt[DD][36];

    const int b   = blockIdx.y;
    const int tid = threadIdx.x;
    const bool isQ = blockIdx.x >= (KN / RT);
    const int r0  = (isQ ? (blockIdx.x - KN / RT) : blockIdx.x) * RT;
    const float* W    = isQ ? Wq : Wk;
    const float* rows = isQ ? (queries + (size_t)(b * QN + r0) * DD)
                            : (keys    + (size_t)(b * KN + r0) * DD);

    #pragma unroll
    for (int i = 0; i < 8; i++) {
        int idx = tid + i * 512;
        srt[idx & 127][idx >> 7] = rows[idx];
    }
    __syncthreads();

    if (!isQ) {
        const int kt = tid >> 7, ht = tid & 127;
        float acc[8];
        #pragma unroll
        for (int i = 0; i < 8; i++) acc[i] = 0.f;
        #pragma unroll 1
        for (int db = 0; db < DD; db += 8) {
            float wb[8];
            #pragma unroll
            for (int j = 0; j < 8; j++)
                wb[j] = W[(db + j) * HN + ht];
            #pragma unroll
            for (int j = 0; j < 8; j++) {
                const float4* s4 = (const float4*)&srt[db + j][0];
                float4 ka = s4[kt * 2], kb = s4[kt * 2 + 1];
                float w = wb[j];
                acc[0] = fmaf(ka.x, w, acc[0]);
                acc[1] = fmaf(ka.y, w, acc[1]);
                acc[2] = fmaf(ka.z, w, acc[2]);
                acc[3] = fmaf(ka.w, w, acc[3]);
                acc[4] = fmaf(kb.x, w, acc[4]);
                acc[5] = fmaf(kb.y, w, acc[5]);
                acc[6] = fmaf(kb.z, w, acc[6]);
                acc[7] = fmaf(kb.w, w, acc[7]);
            }
        }
        __syncthreads();
        #pragma unroll
        for (int i = 0; i < 8; i++)
            srt[ht][kt * 8 + i] = __uint_as_float(pack_h2(acc[i], acc[i]));
        __syncthreads();
        #pragma unroll
        for (int i = 0; i < 2; i++) {
            int t = tid + i * 512;
            int h = t >> 3, k4 = t & 7;
            float4 v = *(const float4*)&srt[h][k4 * 4];
            *(float4*)&g_kpt[(size_t)(b * HN + h) * KN + r0 + k4 * 4] = v;
        }
    } else {
        const int qt = tid >> 5, ht2 = tid & 31;
        float acc[2][4];
        #pragma unroll
        for (int j = 0; j < 2; j++)
            #pragma unroll
            for (int i = 0; i < 4; i++) acc[j][i] = 0.f;
        #pragma unroll 1
        for (int db = 0; db < DD; db += 4) {
            float4 w4[4];
            #pragma unroll
            for (int j = 0; j < 4; j++)
                w4[j] = *(const float4*)&W[(db + j) * HN + ht2 * 4];
            #pragma unroll
            for (int j = 0; j < 4; j++) {
                float2 qv = *(const float2*)&srt[db + j][qt * 2];
                acc[0][0] = fmaf(qv.x, w4[j].x, acc[0][0]);
                acc[0][1] = fmaf(qv.x, w4[j].y, acc[0][1]);
                acc[0][2] = fmaf(qv.x, w4[j].z, acc[0][2]);
                acc[0][3] = fmaf(qv.x, w4[j].w, acc[0][3]);
                acc[1][0] = fmaf(qv.y, w4[j].x, acc[1][0]);
                acc[1][1] = fmaf(qv.y, w4[j].y, acc[1][1]);
                acc[1][2] = fmaf(qv.y, w4[j].z, acc[1][2]);
                acc[1][3] = fmaf(qv.y, w4[j].w, acc[1][3]);
            }
        }
        #pragma unroll
        for (int j = 0; j < 2; j++) {
            float* op = &g_qh[(size_t)(b * QN + r0 + qt * 2 + j) * HN + ht2 * 4];
            *(float4*)op = make_float4(acc[j][0], acc[j][1], acc[j][2], acc[j][3]);
        }
    }
}

// ---------------------------------------------------------------------------
// attn_kernel: 1-D grid of 256 blocks; (b, q-tile) looked up from g_perm.
// Masked keys skip all phase-1 work; phase-2 groups beyond vlen skipped.
// ---------------------------------------------------------------------------
__global__ __launch_bounds__(512, 2) void attn_kernel(
    const float* __restrict__ values, const int* __restrict__ valid_lens,
    const float* __restrict__ wv, float* __restrict__ out)
{
    __shared__ float    sc[QT * KN];
    __shared__ float    part[QT * 512];
    __shared__ unsigned sqh2[HN * 4];
    __shared__ unsigned swv2[HN];
    __shared__ float    redv[QT * 16];
    __shared__ float    smax[QT], sinv[QT];

    const int item = g_perm[blockIdx.x];
    const int b = item >> 4, q0 = (item & 15) * QT;
    const int tid = threadIdx.x;
    const float LOG2E = 1.4426950408889634f;

    const int vlen = __ldg(&valid_lens[b]);

    {   // stage q-projection pairs as f16x2
        int h = tid >> 2, p = tid & 3;
        const float* qb = &g_qh[(size_t)(b * QN + q0 + 2 * p) * HN + h];
        float qlo = qb[0], qhi = qb[HN];
        sqh2[h * 4 + p] = pack_h2(qhi, qlo);
    }
    if (tid < HN) {
        float w = wv[tid];
        swv2[tid] = pack_h2(w, w);
    }
    __syncthreads();

    // ---- phase 1: scores. Only valid keys compute; kv batch 8 ----
    const int k = tid;
    const unsigned* kp = (const unsigned*)&g_kpt[(size_t)(b * HN) * KN + k];
    const bool active = (k < vlen);
    const int hmax = active ? HN : 0;
    float s[QT];
    #pragma unroll
    for (int q = 0; q < QT; q++) s[q] = 0.f;

    #pragma unroll 1
    for (int hb = 0; hb < hmax; hb += 8) {
        unsigned kv2[8];
        #pragma unroll
        for (int j = 0; j < 8; j++)
            kv2[j] = kp[(size_t)(hb + j) * KN];
        unsigned acc2[4] = {0u, 0u, 0u, 0u};
        #pragma unroll
        for (int j = 0; j < 8; j++) {
            const int h = hb + j;
            const unsigned w2 = swv2[h];
            uint4 qp = *(const uint4*)&sqh2[h * 4];
            acc2[0] = hfma2(w2, tanh2(hadd2(kv2[j], qp.x)), acc2[0]);
            acc2[1] = hfma2(w2, tanh2(hadd2(kv2[j], qp.y)), acc2[1]);
            acc2[2] = hfma2(w2, tanh2(hadd2(kv2[j], qp.z)), acc2[2]);
            acc2[3] = hfma2(w2, tanh2(hadd2(kv2[j], qp.w)), acc2[3]);
        }
        float lo, hi;
        unpack_h2(acc2[0], lo, hi); s[0] += lo; s[1] += hi;
        unpack_h2(acc2[1], lo, hi); s[2] += lo; s[3] += hi;
        unpack_h2(acc2[2], lo, hi); s[4] += lo; s[5] += hi;
        unpack_h2(acc2[3], lo, hi); s[6] += lo; s[7] += hi;
    }

    if (!active) {
        #pragma unroll
        for (int q = 0; q < QT; q++) s[q] = -1000000.0f;
    }

    // ---- masked softmax over 512 keys, 8 queries ----
    {
        float mx[QT];
        #pragma unroll
        for (int q = 0; q < QT; q++) mx[q] = s[q];
        #pragma unroll
        for (int off = 16; off; off >>= 1)
            #pragma unroll
            for (int q = 0; q < QT; q++)
                mx[q] = fmaxf(mx[q], __shfl_xor_sync(0xFFFFFFFFu, mx[q], off));
        if ((tid & 31) == 0)
            #pragma unroll
            for (int q = 0; q < QT; q++) redv[q * 16 + (tid >> 5)] = mx[q];
    }
    __syncthreads();
    if (tid < 128) {
        int q = tid >> 4, w = tid & 15;
        float m = redv[q * 16 + w];
        #pragma unroll
        for (int off = 8; off; off >>= 1)
            m = fmaxf(m, __shfl_xor_sync(0xFFFFFFFFu, m, off));
        if (w == 0) smax[q] = m;
    }
    __syncthreads();

    float p[QT];
    {
        float sm[QT];
        #pragma unroll
        for (int q = 0; q < QT; q++) {
            p[q] = ex2f((s[q] - smax[q]) * LOG2E);
            sm[q] = p[q];
        }
        #pragma unroll
        for (int off = 16; off; off >>= 1)
            #pragma unroll
            for (int q = 0; q < QT; q++)
                sm[q] += __shfl_xor_sync(0xFFFFFFFFu, sm[q], off);
        if ((tid & 31) == 0)
            #pragma unroll
            for (int q = 0; q < QT; q++) redv[q * 16 + (tid >> 5)] = sm[q];
    }
    __syncthreads();
    if (tid < 128) {
        int q = tid >> 4, w = tid & 15;
        float t = redv[q * 16 + w];
        #pragma unroll
        for (int off = 8; off; off >>= 1)
            t += __shfl_xor_sync(0xFFFFFFFFu, t, off);
        if (w == 0) sinv[q] = 1.0f / t;
    }
    __syncthreads();
    #pragma unroll
    for (int q = 0; q < QT; q++) sc[q * KN + k] = p[q] * sinv[q];
    __syncthreads();

    // ---- phase 2: out = attn @ values. Skip key-groups beyond vlen ----
    {
        const int v = tid & 127, g = tid >> 7;
        const float* vp = values + (size_t)(b * KN + g * 128) * DD + v;
        float a[QT];
        #pragma unroll
        for (int q = 0; q < QT; q++) a[q] = 0.f;

        int rem = vlen - g * 128;
        int kklim = rem >= 128 ? 128 : (rem > 0 ? ((rem + 7) & ~7) : 0);

        #pragma unroll 1
        for (int kk = 0; kk < kklim; kk += 8) {
            float vv[8];
            #pragma unroll
            for (int j = 0; j < 8; j++)
                vv[j] = vp[(size_t)(kk + j) * DD];
            const int ki = g * 128 + kk;
            #pragma unroll
            for (int q = 0; q < QT; q++) {
                float4 c0 = *(const float4*)&sc[q * KN + ki];
                float4 c1 = *(const float4*)&sc[q * KN + ki + 4];
                a[q] = fmaf(c0.x, vv[0], a[q]);
                a[q] = fmaf(c0.y, vv[1], a[q]);
                a[q] = fmaf(c0.z, vv[2], a[q]);
                a[q] = fmaf(c0.w, vv[3], a[q]);
                a[q] = fmaf(c1.x, vv[4], a[q]);
                a[q] = fmaf(c1.y, vv[5], a[q]);
                a[q] = fmaf(c1.z, vv[6], a[q]);
                a[q] = fmaf(c1.w, vv[7], a[q]);
            }
        }
        #pragma unroll
        for (int q = 0; q < QT; q++) part[q * 512 + tid] = a[q];
    }
    __syncthreads();
    #pragma unroll
    for (int i = 0; i < 2; i++) {
        int t = tid + i * 512;
        int q = t >> 7, v = t & 127;
        const float* pq = &part[q * 512];
        out[(size_t)(b * QN + q0 + q) * DD + v] =
            (pq[v] + pq[128 + v]) + (pq[256 + v] + pq[384 + v]);
    }
}

extern "C" void kernel_launch(void* const* d_in, const int* in_sizes, int n_in,
                              void* d_out, int out_size)
{
    const float* queries = (const float*)d_in[0];
    const float* keys    = (const float*)d_in[1];
    const float* values  = (const float*)d_in[2];
    const int*   vlens   = (const int*)  d_in[3];
    const float* Wq      = (const float*)d_in[4];
    const float* Wk      = (const float*)d_in[5];
    const float* wv      = (const float*)d_in[6];
    float* out = (float*)d_out;

    sched_kernel<<<1, 32>>>(vlens);
    proj_kernel<<<dim3(KN / RT + QN / RT, BB), 512>>>(keys, queries, Wk, Wq);
    attn_kernel<<<(QN / QT) * BB, 512>>>(values, vlens, wv, out);
}

// round 15
// speedup vs baseline: 1.9292x; 1.0283x over previous
#include <cuda_runtime.h>

#define BB 16
#define QN 128
#define KN 512
#define HN 128
#define DD 128
#define QT 8
#define RT 32          // proj row-tile

// scratch: g_kpt holds f16x2-packed {kv,kv} per element, layout [b][h][k]
__device__ float g_kpt[BB * HN * KN];
__device__ float g_qh [BB * QN * HN];
__device__ int   g_perm[(QN / QT) * BB];   // block id -> work item (b*16 + qtile)

__device__ __forceinline__ float ex2f(float x) {
    float r; asm("ex2.approx.f32 %0, %1;" : "=f"(r) : "f"(x)); return r;
}
__device__ __forceinline__ unsigned pack_h2(float hi, float lo) {
    unsigned r; asm("cvt.rn.f16x2.f32 %0, %1, %2;" : "=r"(r) : "f"(hi), "f"(lo)); return r;
}
__device__ __forceinline__ unsigned hadd2(unsigned a, unsigned b) {
    unsigned r; asm("add.f16x2 %0, %1, %2;" : "=r"(r) : "r"(a), "r"(b)); return r;
}
__device__ __forceinline__ unsigned hfma2(unsigned a, unsigned b, unsigned c) {
    unsigned r; asm("fma.rn.f16x2 %0, %1, %2, %3;" : "=r"(r) : "r"(a), "r"(b), "r"(c)); return r;
}
__device__ __forceinline__ unsigned tanh2(unsigned x) {
    unsigned r; asm("tanh.approx.f16x2 %0, %1;" : "=r"(r) : "r"(x)); return r;
}
__device__ __forceinline__ void unpack_h2(unsigned x, float& lo, float& hi) {
    asm("{\n\t.reg .f16 l, h;\n\tmov.b32 {l, h}, %2;\n\t"
        "cvt.f32.f16 %0, l;\n\tcvt.f32.f16 %1, h;\n\t}"
        : "=f"(lo), "=f"(hi) : "r"(x));
}

// ---------------------------------------------------------------------------
// proj_kernel: rows staged in smem; W from L2 with coalesced batched LDGs.
// Key path packs f16x2 before the transposed store.
// Block (0,0) additionally builds the load-balanced attn schedule in g_perm:
// classic placement maps bid and bid+148 to the same SM, so pair sorted rank
// s with rank 255-s (heaviest with lightest); singles take middle ranks.
// Each of 256 threads redundantly ranks the 16 batches and writes one entry.
// ---------------------------------------------------------------------------
__global__ __launch_bounds__(512) void proj_kernel(
    const float* __restrict__ keys, const float* __restrict__ queries,
    const float* __restrict__ Wk,   const float* __restrict__ Wq,
    const int*   __restrict__ vlens)
{
    __shared__ float srt[DD][36];

    const int b   = blockIdx.y;
    const int tid = threadIdx.x;

    if (blockIdx.x == 0 && blockIdx.y == 0 && tid < 256) {
        int v[BB], order[BB];
        #pragma unroll
        for (int i = 0; i < BB; i++) v[i] = __ldg(&vlens[i]);
        #pragma unroll
        for (int i = 0; i < BB; i++) {
            int r = 0;
            #pragma unroll
            for (int j = 0; j < BB; j++)
                if (v[j] > v[i] || (v[j] == v[i] && j < i)) r++;
            order[r] = i;
        }
        // perm index tid: ranks [0,148) direct, [148,256) mirrored partner
        int p = (tid < 148) ? tid : (403 - tid);
        g_perm[tid] = order[p >> 4] * 16 + (p & 15);
    }

    const bool isQ = blockIdx.x >= (KN / RT);
    const int r0  = (isQ ? (blockIdx.x - KN / RT) : blockIdx.x) * RT;
    const float* W    = isQ ? Wq : Wk;
    const float* rows = isQ ? (queries + (size_t)(b * QN + r0) * DD)
                            : (keys    + (size_t)(b * KN + r0) * DD);

    #pragma unroll
    for (int i = 0; i < 8; i++) {
        int idx = tid + i * 512;
        srt[idx & 127][idx >> 7] = rows[idx];
    }
    __syncthreads();

    if (!isQ) {
        const int kt = tid >> 7, ht = tid & 127;
        float acc[8];
        #pragma unroll
        for (int i = 0; i < 8; i++) acc[i] = 0.f;
        #pragma unroll 1
        for (int db = 0; db < DD; db += 8) {
            float wb[8];
            #pragma unroll
            for (int j = 0; j < 8; j++)
                wb[j] = W[(db + j) * HN + ht];
            #pragma unroll
            for (int j = 0; j < 8; j++) {
                const float4* s4 = (const float4*)&srt[db + j][0];
                float4 ka = s4[kt * 2], kb = s4[kt * 2 + 1];
                float w = wb[j];
                acc[0] = fmaf(ka.x, w, acc[0]);
                acc[1] = fmaf(ka.y, w, acc[1]);
                acc[2] = fmaf(ka.z, w, acc[2]);
                acc[3] = fmaf(ka.w, w, acc[3]);
                acc[4] = fmaf(kb.x, w, acc[4]);
                acc[5] = fmaf(kb.y, w, acc[5]);
                acc[6] = fmaf(kb.z, w, acc[6]);
                acc[7] = fmaf(kb.w, w, acc[7]);
            }
        }
        __syncthreads();
        #pragma unroll
        for (int i = 0; i < 8; i++)
            srt[ht][kt * 8 + i] = __uint_as_float(pack_h2(acc[i], acc[i]));
        __syncthreads();
        #pragma unroll
        for (int i = 0; i < 2; i++) {
            int t = tid + i * 512;
            int h = t >> 3, k4 = t & 7;
            float4 v = *(const float4*)&srt[h][k4 * 4];
            *(float4*)&g_kpt[(size_t)(b * HN + h) * KN + r0 + k4 * 4] = v;
        }
    } else {
        const int qt = tid >> 5, ht2 = tid & 31;
        float acc[2][4];
        #pragma unroll
        for (int j = 0; j < 2; j++)
            #pragma unroll
            for (int i = 0; i < 4; i++) acc[j][i] = 0.f;
        #pragma unroll 1
        for (int db = 0; db < DD; db += 4) {
            float4 w4[4];
            #pragma unroll
            for (int j = 0; j < 4; j++)
                w4[j] = *(const float4*)&W[(db + j) * HN + ht2 * 4];
            #pragma unroll
            for (int j = 0; j < 4; j++) {
                float2 qv = *(const float2*)&srt[db + j][qt * 2];
                acc[0][0] = fmaf(qv.x, w4[j].x, acc[0][0]);
                acc[0][1] = fmaf(qv.x, w4[j].y, acc[0][1]);
                acc[0][2] = fmaf(qv.x, w4[j].z, acc[0][2]);
                acc[0][3] = fmaf(qv.x, w4[j].w, acc[0][3]);
                acc[1][0] = fmaf(qv.y, w4[j].x, acc[1][0]);
                acc[1][1] = fmaf(qv.y, w4[j].y, acc[1][1]);
                acc[1][2] = fmaf(qv.y, w4[j].z, acc[1][2]);
                acc[1][3] = fmaf(qv.y, w4[j].w, acc[1][3]);
            }
        }
        #pragma unroll
        for (int j = 0; j < 2; j++) {
            float* op = &g_qh[(size_t)(b * QN + r0 + qt * 2 + j) * HN + ht2 * 4];
            *(float4*)op = make_float4(acc[j][0], acc[j][1], acc[j][2], acc[j][3]);
        }
    }
}

// ---------------------------------------------------------------------------
// attn_kernel: 1-D grid of 256 blocks; (b, q-tile) looked up from g_perm.
// Masked keys skip all phase-1 work; phase-2 groups beyond vlen skipped.
// ---------------------------------------------------------------------------
__global__ __launch_bounds__(512, 2) void attn_kernel(
    const float* __restrict__ values, const int* __restrict__ valid_lens,
    const float* __restrict__ wv, float* __restrict__ out)
{
    __shared__ float    sc[QT * KN];
    __shared__ float    part[QT * 512];
    __shared__ unsigned sqh2[HN * 4];
    __shared__ unsigned swv2[HN];
    __shared__ float    redv[QT * 16];
    __shared__ float    smax[QT], sinv[QT];

    const int item = g_perm[blockIdx.x];
    const int b = item >> 4, q0 = (item & 15) * QT;
    const int tid = threadIdx.x;
    const float LOG2E = 1.4426950408889634f;

    const int vlen = __ldg(&valid_lens[b]);

    {   // stage q-projection pairs as f16x2
        int h = tid >> 2, p = tid & 3;
        const float* qb = &g_qh[(size_t)(b * QN + q0 + 2 * p) * HN + h];
        float qlo = qb[0], qhi = qb[HN];
        sqh2[h * 4 + p] = pack_h2(qhi, qlo);
    }
    if (tid < HN) {
        float w = wv[tid];
        swv2[tid] = pack_h2(w, w);
    }
    __syncthreads();

    // ---- phase 1: scores. Only valid keys compute; kv batch 8 ----
    const int k = tid;
    const unsigned* kp = (const unsigned*)&g_kpt[(size_t)(b * HN) * KN + k];
    const bool active = (k < vlen);
    const int hmax = active ? HN : 0;
    float s[QT];
    #pragma unroll
    for (int q = 0; q < QT; q++) s[q] = 0.f;

    #pragma unroll 1
    for (int hb = 0; hb < hmax; hb += 8) {
        unsigned kv2[8];
        #pragma unroll
        for (int j = 0; j < 8; j++)
            kv2[j] = kp[(size_t)(hb + j) * KN];
        unsigned acc2[4] = {0u, 0u, 0u, 0u};
        #pragma unroll
        for (int j = 0; j < 8; j++) {
            const int h = hb + j;
            const unsigned w2 = swv2[h];
            uint4 qp = *(const uint4*)&sqh2[h * 4];
            acc2[0] = hfma2(w2, tanh2(hadd2(kv2[j], qp.x)), acc2[0]);
            acc2[1] = hfma2(w2, tanh2(hadd2(kv2[j], qp.y)), acc2[1]);
            acc2[2] = hfma2(w2, tanh2(hadd2(kv2[j], qp.z)), acc2[2]);
            acc2[3] = hfma2(w2, tanh2(hadd2(kv2[j], qp.w)), acc2[3]);
        }
        float lo, hi;
        unpack_h2(acc2[0], lo, hi); s[0] += lo; s[1] += hi;
        unpack_h2(acc2[1], lo, hi); s[2] += lo; s[3] += hi;
        unpack_h2(acc2[2], lo, hi); s[4] += lo; s[5] += hi;
        unpack_h2(acc2[3], lo, hi); s[6] += lo; s[7] += hi;
    }

    if (!active) {
        #pragma unroll
        for (int q = 0; q < QT; q++) s[q] = -1000000.0f;
    }

    // ---- masked softmax over 512 keys, 8 queries ----
    {
        float mx[QT];
        #pragma unroll
        for (int q = 0; q < QT; q++) mx[q] = s[q];
        #pragma unroll
        for (int off = 16; off; off >>= 1)
            #pragma unroll
            for (int q = 0; q < QT; q++)
                mx[q] = fmaxf(mx[q], __shfl_xor_sync(0xFFFFFFFFu, mx[q], off));
        if ((tid & 31) == 0)
            #pragma unroll
            for (int q = 0; q < QT; q++) redv[q * 16 + (tid >> 5)] = mx[q];
    }
    __syncthreads();
    if (tid < 128) {
        int q = tid >> 4, w = tid & 15;
        float m = redv[q * 16 + w];
        #pragma unroll
        for (int off = 8; off; off >>= 1)
            m = fmaxf(m, __shfl_xor_sync(0xFFFFFFFFu, m, off));
        if (w == 0) smax[q] = m;
    }
    __syncthreads();

    float p[QT];
    {
        float sm[QT];
        #pragma unroll
        for (int q = 0; q < QT; q++) {
            p[q] = ex2f((s[q] - smax[q]) * LOG2E);
            sm[q] = p[q];
        }
        #pragma unroll
        for (int off = 16; off; off >>= 1)
            #pragma unroll
            for (int q = 0; q < QT; q++)
                sm[q] += __shfl_xor_sync(0xFFFFFFFFu, sm[q], off);
        if ((tid & 31) == 0)
            #pragma unroll
            for (int q = 0; q < QT; q++) redv[q * 16 + (tid >> 5)] = sm[q];
    }
    __syncthreads();
    if (tid < 128) {
        int q = tid >> 4, w = tid & 15;
        float t = redv[q * 16 + w];
        #pragma unroll
        for (int off = 8; off; off >>= 1)
            t += __shfl_xor_sync(0xFFFFFFFFu, t, off);
        if (w == 0) sinv[q] = 1.0f / t;
    }
    __syncthreads();
    #pragma unroll
    for (int q = 0; q < QT; q++) sc[q * KN + k] = p[q] * sinv[q];
    __syncthreads();

    // ---- phase 2: out = attn @ values. Skip key-groups beyond vlen ----
    {
        const int v = tid & 127, g = tid >> 7;
        const float* vp = values + (size_t)(b * KN + g * 128) * DD + v;
        float a[QT];
        #pragma unroll
        for (int q = 0; q < QT; q++) a[q] = 0.f;

        int rem = vlen - g * 128;
        int kklim = rem >= 128 ? 128 : (rem > 0 ? ((rem + 7) & ~7) : 0);

        #pragma unroll 1
        for (int kk = 0; kk < kklim; kk += 8) {
            float vv[8];
            #pragma unroll
            for (int j = 0; j < 8; j++)
                vv[j] = vp[(size_t)(kk + j) * DD];
            const int ki = g * 128 + kk;
            #pragma unroll
            for (int q = 0; q < QT; q++) {
                float4 c0 = *(const float4*)&sc[q * KN + ki];
                float4 c1 = *(const float4*)&sc[q * KN + ki + 4];
                a[q] = fmaf(c0.x, vv[0], a[q]);
                a[q] = fmaf(c0.y, vv[1], a[q]);
                a[q] = fmaf(c0.z, vv[2], a[q]);
                a[q] = fmaf(c0.w, vv[3], a[q]);
                a[q] = fmaf(c1.x, vv[4], a[q]);
                a[q] = fmaf(c1.y, vv[5], a[q]);
                a[q] = fmaf(c1.z, vv[6], a[q]);
                a[q] = fmaf(c1.w, vv[7], a[q]);
            }
        }
        #pragma unroll
        for (int q = 0; q < QT; q++) part[q * 512 + tid] = a[q];
    }
    __syncthreads();
    #pragma unroll
    for (int i = 0; i < 2; i++) {
        int t = tid + i * 512;
        int q = t >> 7, v = t & 127;
        const float* pq = &part[q * 512];
        out[(size_t)(b * QN + q0 + q) * DD + v] =
            (pq[v] + pq[128 + v]) + (pq[256 + v] + pq[384 + v]);
    }
}

extern "C" void kernel_launch(void* const* d_in, const int* in_sizes, int n_in,
                              void* d_out, int out_size)
{
    const float* queries = (const float*)d_in[0];
    const float* keys    = (const float*)d_in[1];
    const float* values  = (const float*)d_in[2];
    const int*   vlens   = (const int*)  d_in[3];
    const float* Wq      = (const float*)d_in[4];
    const float* Wk      = (const float*)d_in[5];
    const float* wv      = (const float*)d_in[6];
    float* out = (float*)d_out;

    proj_kernel<<<dim3(KN / RT + QN / RT, BB), 512>>>(keys, queries, Wk, Wq, vlens);
    attn_kernel<<<(QN / QT) * BB, 512>>>(values, vlens, wv, out);
}

// round 16
// speedup vs baseline: 1.9476x; 1.0095x over previous
#include <cuda_runtime.h>

#define BB 16
#define QN 128
#define KN 512
#define HN 128
#define DD 128
#define QT 8
#define RT 32          // proj row-tile

// scratch: g_kpt holds f16x2-packed {kv,kv} per element, layout [b][h][k]
__device__ float g_kpt[BB * HN * KN];
__device__ float g_qh [BB * QN * HN];
__device__ int   g_perm[(QN / QT) * BB];   // block id -> work item (b*16 + qtile)

__device__ __forceinline__ float ex2f(float x) {
    float r; asm("ex2.approx.f32 %0, %1;" : "=f"(r) : "f"(x)); return r;
}
__device__ __forceinline__ unsigned pack_h2(float hi, float lo) {
    unsigned r; asm("cvt.rn.f16x2.f32 %0, %1, %2;" : "=r"(r) : "f"(hi), "f"(lo)); return r;
}
__device__ __forceinline__ unsigned hadd2(unsigned a, unsigned b) {
    unsigned r; asm("add.f16x2 %0, %1, %2;" : "=r"(r) : "r"(a), "r"(b)); return r;
}
__device__ __forceinline__ unsigned hfma2(unsigned a, unsigned b, unsigned c) {
    unsigned r; asm("fma.rn.f16x2 %0, %1, %2, %3;" : "=r"(r) : "r"(a), "r"(b), "r"(c)); return r;
}
__device__ __forceinline__ unsigned tanh2(unsigned x) {
    unsigned r; asm("tanh.approx.f16x2 %0, %1;" : "=r"(r) : "r"(x)); return r;
}
__device__ __forceinline__ void unpack_h2(unsigned x, float& lo, float& hi) {
    asm("{\n\t.reg .f16 l, h;\n\tmov.b32 {l, h}, %2;\n\t"
        "cvt.f32.f16 %0, l;\n\tcvt.f32.f16 %1, h;\n\t}"
        : "=f"(lo), "=f"(hi) : "r"(x));
}

// ---------------------------------------------------------------------------
// proj_kernel: rows staged in smem; W from L2 with coalesced batched LDGs.
// Key path packs f16x2 before the transposed store. Block (0,0) also builds
// the load-balanced attn schedule in g_perm (bid and bid+148 share an SM:
// pair sorted rank s with rank 255-s).
// ---------------------------------------------------------------------------
__global__ __launch_bounds__(512) void proj_kernel(
    const float* __restrict__ keys, const float* __restrict__ queries,
    const float* __restrict__ Wk,   const float* __restrict__ Wq,
    const int*   __restrict__ vlens)
{
    __shared__ float srt[DD][36];

    const int b   = blockIdx.y;
    const int tid = threadIdx.x;

    if (blockIdx.x == 0 && blockIdx.y == 0 && tid < 256) {
        int v[BB], order[BB];
        #pragma unroll
        for (int i = 0; i < BB; i++) v[i] = __ldg(&vlens[i]);
        #pragma unroll
        for (int i = 0; i < BB; i++) {
            int r = 0;
            #pragma unroll
            for (int j = 0; j < BB; j++)
                if (v[j] > v[i] || (v[j] == v[i] && j < i)) r++;
            order[r] = i;
        }
        int p = (tid < 148) ? tid : (403 - tid);
        g_perm[tid] = order[p >> 4] * 16 + (p & 15);
    }

    const bool isQ = blockIdx.x >= (KN / RT);
    const int r0  = (isQ ? (blockIdx.x - KN / RT) : blockIdx.x) * RT;
    const float* W    = isQ ? Wq : Wk;
    const float* rows = isQ ? (queries + (size_t)(b * QN + r0) * DD)
                            : (keys    + (size_t)(b * KN + r0) * DD);

    #pragma unroll
    for (int i = 0; i < 8; i++) {
        int idx = tid + i * 512;
        srt[idx & 127][idx >> 7] = rows[idx];
    }
    __syncthreads();

    if (!isQ) {
        const int kt = tid >> 7, ht = tid & 127;
        float acc[8];
        #pragma unroll
        for (int i = 0; i < 8; i++) acc[i] = 0.f;
        #pragma unroll 1
        for (int db = 0; db < DD; db += 8) {
            float wb[8];
            #pragma unroll
            for (int j = 0; j < 8; j++)
                wb[j] = W[(db + j) * HN + ht];
            #pragma unroll
            for (int j = 0; j < 8; j++) {
                const float4* s4 = (const float4*)&srt[db + j][0];
                float4 ka = s4[kt * 2], kb = s4[kt * 2 + 1];
                float w = wb[j];
                acc[0] = fmaf(ka.x, w, acc[0]);
                acc[1] = fmaf(ka.y, w, acc[1]);
                acc[2] = fmaf(ka.z, w, acc[2]);
                acc[3] = fmaf(ka.w, w, acc[3]);
                acc[4] = fmaf(kb.x, w, acc[4]);
                acc[5] = fmaf(kb.y, w, acc[5]);
                acc[6] = fmaf(kb.z, w, acc[6]);
                acc[7] = fmaf(kb.w, w, acc[7]);
            }
        }
        __syncthreads();
        #pragma unroll
        for (int i = 0; i < 8; i++)
            srt[ht][kt * 8 + i] = __uint_as_float(pack_h2(acc[i], acc[i]));
        __syncthreads();
        #pragma unroll
        for (int i = 0; i < 2; i++) {
            int t = tid + i * 512;
            int h = t >> 3, k4 = t & 7;
            float4 v = *(const float4*)&srt[h][k4 * 4];
            *(float4*)&g_kpt[(size_t)(b * HN + h) * KN + r0 + k4 * 4] = v;
        }
    } else {
        const int qt = tid >> 5, ht2 = tid & 31;
        float acc[2][4];
        #pragma unroll
        for (int j = 0; j < 2; j++)
            #pragma unroll
            for (int i = 0; i < 4; i++) acc[j][i] = 0.f;
        #pragma unroll 1
        for (int db = 0; db < DD; db += 4) {
            float4 w4[4];
            #pragma unroll
            for (int j = 0; j < 4; j++)
                w4[j] = *(const float4*)&W[(db + j) * HN + ht2 * 4];
            #pragma unroll
            for (int j = 0; j < 4; j++) {
                float2 qv = *(const float2*)&srt[db + j][qt * 2];
                acc[0][0] = fmaf(qv.x, w4[j].x, acc[0][0]);
                acc[0][1] = fmaf(qv.x, w4[j].y, acc[0][1]);
                acc[0][2] = fmaf(qv.x, w4[j].z, acc[0][2]);
                acc[0][3] = fmaf(qv.x, w4[j].w, acc[0][3]);
                acc[1][0] = fmaf(qv.y, w4[j].x, acc[1][0]);
                acc[1][1] = fmaf(qv.y, w4[j].y, acc[1][1]);
                acc[1][2] = fmaf(qv.y, w4[j].z, acc[1][2]);
                acc[1][3] = fmaf(qv.y, w4[j].w, acc[1][3]);
            }
        }
        #pragma unroll
        for (int j = 0; j < 2; j++) {
            float* op = &g_qh[(size_t)(b * QN + r0 + qt * 2 + j) * HN + ht2 * 4];
            *(float4*)op = make_float4(acc[j][0], acc[j][1], acc[j][2], acc[j][3]);
        }
    }
}

// ---------------------------------------------------------------------------
// attn_kernel: 1-D grid of 256 blocks; (b, q-tile) from g_perm.
// Small-vlen blocks split the h-range across thread segments (S=2 or 4) so
// active warp density stays high; partial scores reduced through sc scratch.
// ---------------------------------------------------------------------------
__global__ __launch_bounds__(512, 2) void attn_kernel(
    const float* __restrict__ values, const int* __restrict__ valid_lens,
    const float* __restrict__ wv, float* __restrict__ out)
{
    __shared__ float    sc[QT * KN];     // scratch for seg-reduce, then weights
    __shared__ float    part[QT * 512];
    __shared__ unsigned sqh2[HN * 4];
    __shared__ unsigned swv2[HN];
    __shared__ float    redv[QT * 16];
    __shared__ float    smax[QT], sinv[QT];

    const int item = g_perm[blockIdx.x];
    const int b = item >> 4, q0 = (item & 15) * QT;
    const int tid = threadIdx.x;
    const float LOG2E = 1.4426950408889634f;

    const int vlen = __ldg(&valid_lens[b]);

    {   // stage q-projection pairs as f16x2
        int h = tid >> 2, p = tid & 3;
        const float* qb = &g_qh[(size_t)(b * QN + q0 + 2 * p) * HN + h];
        float qlo = qb[0], qhi = qb[HN];
        sqh2[h * 4 + p] = pack_h2(qhi, qlo);
    }
    if (tid < HN) {
        float w = wv[tid];
        swv2[tid] = pack_h2(w, w);
    }
    __syncthreads();

    // ---- phase 1: scores with h-splitting for small vlen ----
    int logK;                       // keys covered = 1<<logK; S = 512>>logK
    if (vlen <= 128)      logK = 7;   // S=4, 32 h per segment
    else if (vlen <= 256) logK = 8;   // S=2, 64 h per segment
    else                  logK = 9;   // S=1
    const int Kp  = 1 << logK;
    const int S   = 512 >> logK;
    const int k   = tid & (Kp - 1);
    const int seg = tid >> logK;
    const bool kvalid = (k < vlen);
    const int hspan = HN >> (9 - logK);          // 128/S
    const int hb0 = seg * hspan;
    const int hb1 = kvalid ? hb0 + hspan : hb0;

    const unsigned* kp = (const unsigned*)&g_kpt[(size_t)(b * HN) * KN + k];
    float s[QT];
    #pragma unroll
    for (int q = 0; q < QT; q++) s[q] = 0.f;

    #pragma unroll 1
    for (int hb = hb0; hb < hb1; hb += 8) {
        unsigned kv2[8];
        #pragma unroll
        for (int j = 0; j < 8; j++)
            kv2[j] = kp[(size_t)(hb + j) * KN];
        unsigned acc2[4] = {0u, 0u, 0u, 0u};
        #pragma unroll
        for (int j = 0; j < 8; j++) {
            const int h = hb + j;
            const unsigned w2 = swv2[h];
            uint4 qp = *(const uint4*)&sqh2[h * 4];
            acc2[0] = hfma2(w2, tanh2(hadd2(kv2[j], qp.x)), acc2[0]);
            acc2[1] = hfma2(w2, tanh2(hadd2(kv2[j], qp.y)), acc2[1]);
            acc2[2] = hfma2(w2, tanh2(hadd2(kv2[j], qp.z)), acc2[2]);
            acc2[3] = hfma2(w2, tanh2(hadd2(kv2[j], qp.w)), acc2[3]);
        }
        float lo, hi;
        unpack_h2(acc2[0], lo, hi); s[0] += lo; s[1] += hi;
        unpack_h2(acc2[1], lo, hi); s[2] += lo; s[3] += hi;
        unpack_h2(acc2[2], lo, hi); s[4] += lo; s[5] += hi;
        unpack_h2(acc2[3], lo, hi); s[6] += lo; s[7] += hi;
    }

    if (S > 1) {    // cross-segment reduction via sc scratch
        #pragma unroll
        for (int q = 0; q < QT; q++) sc[q * KN + tid] = s[q];
        __syncthreads();
        #pragma unroll
        for (int q = 0; q < QT; q++) {
            float t0 = sc[q * KN + k];
            for (int i = 1; i < S; i++) t0 += sc[q * KN + k + i * Kp];
            s[q] = t0;
        }
        __syncthreads();            // sc about to be reused for weights
    }

    if (tid >= vlen) {              // thread tid now represents key tid
        #pragma unroll
        for (int q = 0; q < QT; q++) s[q] = -1000000.0f;
    }

    // ---- masked softmax over 512 keys, 8 queries ----
    {
        float mx[QT];
        #pragma unroll
        for (int q = 0; q < QT; q++) mx[q] = s[q];
        #pragma unroll
        for (int off = 16; off; off >>= 1)
            #pragma unroll
            for (int q = 0; q < QT; q++)
                mx[q] = fmaxf(mx[q], __shfl_xor_sync(0xFFFFFFFFu, mx[q], off));
        if ((tid & 31) == 0)
            #pragma unroll
            for (int q = 0; q < QT; q++) redv[q * 16 + (tid >> 5)] = mx[q];
    }
    __syncthreads();
    if (tid < 128) {
        int q = tid >> 4, w = tid & 15;
        float m = redv[q * 16 + w];
        #pragma unroll
        for (int off = 8; off; off >>= 1)
            m = fmaxf(m, __shfl_xor_sync(0xFFFFFFFFu, m, off));
        if (w == 0) smax[q] = m;
    }
    __syncthreads();

    float p[QT];
    {
        float sm[QT];
        #pragma unroll
        for (int q = 0; q < QT; q++) {
            p[q] = ex2f((s[q] - smax[q]) * LOG2E);
            sm[q] = p[q];
        }
        #pragma unroll
        for (int off = 16; off; off >>= 1)
            #pragma unroll
            for (int q = 0; q < QT; q++)
                sm[q] += __shfl_xor_sync(0xFFFFFFFFu, sm[q], off);
        if ((tid & 31) == 0)
            #pragma unroll
            for (int q = 0; q < QT; q++) redv[q * 16 + (tid >> 5)] = sm[q];
    }
    __syncthreads();
    if (tid < 128) {
        int q = tid >> 4, w = tid & 15;
        float t = redv[q * 16 + w];
        #pragma unroll
        for (int off = 8; off; off >>= 1)
            t += __shfl_xor_sync(0xFFFFFFFFu, t, off);
        if (w == 0) sinv[q] = 1.0f / t;
    }
    __syncthreads();
    #pragma unroll
    for (int q = 0; q < QT; q++) sc[q * KN + tid] = p[q] * sinv[q];
    __syncthreads();

    // ---- phase 2: out = attn @ values. Skip key-groups beyond vlen ----
    {
        const int v = tid & 127, g = tid >> 7;
        const float* vp = values + (size_t)(b * KN + g * 128) * DD + v;
        float a[QT];
        #pragma unroll
        for (int q = 0; q < QT; q++) a[q] = 0.f;

        int rem = vlen - g * 128;
        int kklim = rem >= 128 ? 128 : (rem > 0 ? ((rem + 7) & ~7) : 0);

        #pragma unroll 1
        for (int kk = 0; kk < kklim; kk += 8) {
            float vv[8];
            #pragma unroll
            for (int j = 0; j < 8; j++)
                vv[j] = vp[(size_t)(kk + j) * DD];
            const int ki = g * 128 + kk;
            #pragma unroll
            for (int q = 0; q < QT; q++) {
                float4 c0 = *(const float4*)&sc[q * KN + ki];
                float4 c1 = *(const float4*)&sc[q * KN + ki + 4];
                a[q] = fmaf(c0.x, vv[0], a[q]);
                a[q] = fmaf(c0.y, vv[1], a[q]);
                a[q] = fmaf(c0.z, vv[2], a[q]);
                a[q] = fmaf(c0.w, vv[3], a[q]);
                a[q] = fmaf(c1.x, vv[4], a[q]);
                a[q] = fmaf(c1.y, vv[5], a[q]);
                a[q] = fmaf(c1.z, vv[6], a[q]);
                a[q] = fmaf(c1.w, vv[7], a[q]);
            }
        }
        #pragma unroll
        for (int q = 0; q < QT; q++) part[q * 512 + tid] = a[q];
    }
    __syncthreads();
    #pragma unroll
    for (int i = 0; i < 2; i++) {
        int t = tid + i * 512;
        int q = t >> 7, v = t & 127;
        const float* pq = &part[q * 512];
        out[(size_t)(b * QN + q0 + q) * DD + v] =
            (pq[v] + pq[128 + v]) + (pq[256 + v] + pq[384 + v]);
    }
}

extern "C" void kernel_launch(void* const* d_in, const int* in_sizes, int n_in,
                              void* d_out, int out_size)
{
    const float* queries = (const float*)d_in[0];
    const float* keys    = (const float*)d_in[1];
    const float* values  = (const float*)d_in[2];
    const int*   vlens   = (const int*)  d_in[3];
    const float* Wq      = (const float*)d_in[4];
    const float* Wk      = (const float*)d_in[5];
    const float* wv      = (const float*)d_in[6];
    float* out = (float*)d_out;

    proj_kernel<<<dim3(KN / RT + QN / RT, BB), 512>>>(keys, queries, Wk, Wq, vlens);
    attn_kernel<<<(QN / QT) * BB, 512>>>(values, vlens, wv, out);
}

// round 17
// speedup vs baseline: 2.0148x; 1.0345x over previous
#include <cuda_runtime.h>

#define BB 16
#define QN 128
#define KN 512
#define HN 128
#define DD 128
#define QT 8
#define RT 32          // proj row-tile

// scratch: g_kpt holds f16x2-packed {kv,kv} per element, layout [b][h][k]
__device__ float g_kpt[BB * HN * KN];
__device__ float g_qh [BB * QN * HN];
__device__ int   g_perm[(QN / QT) * BB];   // block id -> work item (b*16 + qtile)

__device__ __forceinline__ float ex2f(float x) {
    float r; asm("ex2.approx.f32 %0, %1;" : "=f"(r) : "f"(x)); return r;
}
__device__ __forceinline__ unsigned pack_h2(float hi, float lo) {
    unsigned r; asm("cvt.rn.f16x2.f32 %0, %1, %2;" : "=r"(r) : "f"(hi), "f"(lo)); return r;
}
__device__ __forceinline__ unsigned hadd2(unsigned a, unsigned b) {
    unsigned r; asm("add.f16x2 %0, %1, %2;" : "=r"(r) : "r"(a), "r"(b)); return r;
}
__device__ __forceinline__ unsigned hfma2(unsigned a, unsigned b, unsigned c) {
    unsigned r; asm("fma.rn.f16x2 %0, %1, %2, %3;" : "=r"(r) : "r"(a), "r"(b), "r"(c)); return r;
}
__device__ __forceinline__ unsigned tanh2(unsigned x) {
    unsigned r; asm("tanh.approx.f16x2 %0, %1;" : "=r"(r) : "r"(x)); return r;
}
__device__ __forceinline__ void unpack_h2(unsigned x, float& lo, float& hi) {
    asm("{\n\t.reg .f16 l, h;\n\tmov.b32 {l, h}, %2;\n\t"
        "cvt.f32.f16 %0, l;\n\tcvt.f32.f16 %1, h;\n\t}"
        : "=f"(lo), "=f"(hi) : "r"(x));
}

// ---------------------------------------------------------------------------
// proj_kernel: rows staged in smem; W from L2 with coalesced batched LDGs.
// Key path packs f16x2 before the transposed store. Block (0,0) also builds
// the load-balanced attn schedule in g_perm (bid and bid+148 share an SM:
// pair sorted rank s with rank 255-s).
// ---------------------------------------------------------------------------
__global__ __launch_bounds__(512) void proj_kernel(
    const float* __restrict__ keys, const float* __restrict__ queries,
    const float* __restrict__ Wk,   const float* __restrict__ Wq,
    const int*   __restrict__ vlens)
{
    __shared__ float srt[DD][36];

    const int b   = blockIdx.y;
    const int tid = threadIdx.x;

    if (blockIdx.x == 0 && blockIdx.y == 0 && tid < 256) {
        int v[BB], order[BB];
        #pragma unroll
        for (int i = 0; i < BB; i++) v[i] = __ldg(&vlens[i]);
        #pragma unroll
        for (int i = 0; i < BB; i++) {
            int r = 0;
            #pragma unroll
            for (int j = 0; j < BB; j++)
                if (v[j] > v[i] || (v[j] == v[i] && j < i)) r++;
            order[r] = i;
        }
        int p = (tid < 148) ? tid : (403 - tid);
        g_perm[tid] = order[p >> 4] * 16 + (p & 15);
    }

    const bool isQ = blockIdx.x >= (KN / RT);
    const int r0  = (isQ ? (blockIdx.x - KN / RT) : blockIdx.x) * RT;
    const float* W    = isQ ? Wq : Wk;
    const float* rows = isQ ? (queries + (size_t)(b * QN + r0) * DD)
                            : (keys    + (size_t)(b * KN + r0) * DD);

    #pragma unroll
    for (int i = 0; i < 8; i++) {
        int idx = tid + i * 512;
        srt[idx & 127][idx >> 7] = rows[idx];
    }
    __syncthreads();

    if (!isQ) {
        const int kt = tid >> 7, ht = tid & 127;
        float acc[8];
        #pragma unroll
        for (int i = 0; i < 8; i++) acc[i] = 0.f;
        #pragma unroll 1
        for (int db = 0; db < DD; db += 8) {
            float wb[8];
            #pragma unroll
            for (int j = 0; j < 8; j++)
                wb[j] = W[(db + j) * HN + ht];
            #pragma unroll
            for (int j = 0; j < 8; j++) {
                const float4* s4 = (const float4*)&srt[db + j][0];
                float4 ka = s4[kt * 2], kb = s4[kt * 2 + 1];
                float w = wb[j];
                acc[0] = fmaf(ka.x, w, acc[0]);
                acc[1] = fmaf(ka.y, w, acc[1]);
                acc[2] = fmaf(ka.z, w, acc[2]);
                acc[3] = fmaf(ka.w, w, acc[3]);
                acc[4] = fmaf(kb.x, w, acc[4]);
                acc[5] = fmaf(kb.y, w, acc[5]);
                acc[6] = fmaf(kb.z, w, acc[6]);
                acc[7] = fmaf(kb.w, w, acc[7]);
            }
        }
        __syncthreads();
        #pragma unroll
        for (int i = 0; i < 8; i++)
            srt[ht][kt * 8 + i] = __uint_as_float(pack_h2(acc[i], acc[i]));
        __syncthreads();
        #pragma unroll
        for (int i = 0; i < 2; i++) {
            int t = tid + i * 512;
            int h = t >> 3, k4 = t & 7;
            float4 v = *(const float4*)&srt[h][k4 * 4];
            *(float4*)&g_kpt[(size_t)(b * HN + h) * KN + r0 + k4 * 4] = v;
        }
    } else {
        const int qt = tid >> 5, ht2 = tid & 31;
        float acc[2][4];
        #pragma unroll
        for (int j = 0; j < 2; j++)
            #pragma unroll
            for (int i = 0; i < 4; i++) acc[j][i] = 0.f;
        #pragma unroll 1
        for (int db = 0; db < DD; db += 4) {
            float4 w4[4];
            #pragma unroll
            for (int j = 0; j < 4; j++)
                w4[j] = *(const float4*)&W[(db + j) * HN + ht2 * 4];
            #pragma unroll
            for (int j = 0; j < 4; j++) {
                float2 qv = *(const float2*)&srt[db + j][qt * 2];
                acc[0][0] = fmaf(qv.x, w4[j].x, acc[0][0]);
                acc[0][1] = fmaf(qv.x, w4[j].y, acc[0][1]);
                acc[0][2] = fmaf(qv.x, w4[j].z, acc[0][2]);
                acc[0][3] = fmaf(qv.x, w4[j].w, acc[0][3]);
                acc[1][0] = fmaf(qv.y, w4[j].x, acc[1][0]);
                acc[1][1] = fmaf(qv.y, w4[j].y, acc[1][1]);
                acc[1][2] = fmaf(qv.y, w4[j].z, acc[1][2]);
                acc[1][3] = fmaf(qv.y, w4[j].w, acc[1][3]);
            }
        }
        #pragma unroll
        for (int j = 0; j < 2; j++) {
            float* op = &g_qh[(size_t)(b * QN + r0 + qt * 2 + j) * HN + ht2 * 4];
            *(float4*)op = make_float4(acc[j][0], acc[j][1], acc[j][2], acc[j][3]);
        }
    }
}

// ---------------------------------------------------------------------------
// attn_kernel: 1-D grid of 256 blocks; (b, q-tile) from g_perm.
// Shift-free softmax (|score| <= ~9 so exp is f32-safe); first phase-2 value
// batch prefetched before the sum reduction; h-split for small vlen.
// ---------------------------------------------------------------------------
__global__ __launch_bounds__(512, 2) void attn_kernel(
    const float* __restrict__ values, const int* __restrict__ valid_lens,
    const float* __restrict__ wv, float* __restrict__ out)
{
    __shared__ float    sc[QT * KN];     // scratch for seg-reduce, then weights
    __shared__ float    part[QT * 512];
    __shared__ unsigned sqh2[HN * 4];
    __shared__ unsigned swv2[HN];
    __shared__ float    redv[QT * 16];
    __shared__ float    sinv[QT];

    const int item = g_perm[blockIdx.x];
    const int b = item >> 4, q0 = (item & 15) * QT;
    const int tid = threadIdx.x;
    const float LOG2E = 1.4426950408889634f;

    const int vlen = __ldg(&valid_lens[b]);

    {   // stage q-projection pairs as f16x2
        int h = tid >> 2, p = tid & 3;
        const float* qb = &g_qh[(size_t)(b * QN + q0 + 2 * p) * HN + h];
        float qlo = qb[0], qhi = qb[HN];
        sqh2[h * 4 + p] = pack_h2(qhi, qlo);
    }
    if (tid < HN) {
        float w = wv[tid];
        swv2[tid] = pack_h2(w, w);
    }
    __syncthreads();

    // ---- phase 1: scores with h-splitting for small vlen ----
    int logK;
    if (vlen <= 128)      logK = 7;   // S=4
    else if (vlen <= 256) logK = 8;   // S=2
    else                  logK = 9;   // S=1
    const int Kp  = 1 << logK;
    const int S   = 512 >> logK;
    const int k   = tid & (Kp - 1);
    const int seg = tid >> logK;
    const bool kvalid = (k < vlen);
    const int hspan = HN >> (9 - logK);
    const int hb0 = seg * hspan;
    const int hb1 = kvalid ? hb0 + hspan : hb0;

    const unsigned* kp = (const unsigned*)&g_kpt[(size_t)(b * HN) * KN + k];
    float s[QT];
    #pragma unroll
    for (int q = 0; q < QT; q++) s[q] = 0.f;

    #pragma unroll 1
    for (int hb = hb0; hb < hb1; hb += 8) {
        unsigned kv2[8];
        #pragma unroll
        for (int j = 0; j < 8; j++)
            kv2[j] = kp[(size_t)(hb + j) * KN];
        unsigned acc2[4] = {0u, 0u, 0u, 0u};
        #pragma unroll
        for (int j = 0; j < 8; j++) {
            const int h = hb + j;
            const unsigned w2 = swv2[h];
            uint4 qp = *(const uint4*)&sqh2[h * 4];
            acc2[0] = hfma2(w2, tanh2(hadd2(kv2[j], qp.x)), acc2[0]);
            acc2[1] = hfma2(w2, tanh2(hadd2(kv2[j], qp.y)), acc2[1]);
            acc2[2] = hfma2(w2, tanh2(hadd2(kv2[j], qp.z)), acc2[2]);
            acc2[3] = hfma2(w2, tanh2(hadd2(kv2[j], qp.w)), acc2[3]);
        }
        float lo, hi;
        unpack_h2(acc2[0], lo, hi); s[0] += lo; s[1] += hi;
        unpack_h2(acc2[1], lo, hi); s[2] += lo; s[3] += hi;
        unpack_h2(acc2[2], lo, hi); s[4] += lo; s[5] += hi;
        unpack_h2(acc2[3], lo, hi); s[6] += lo; s[7] += hi;
    }

    if (S > 1) {    // cross-segment reduction via sc scratch
        #pragma unroll
        for (int q = 0; q < QT; q++) sc[q * KN + tid] = s[q];
        __syncthreads();
        #pragma unroll
        for (int q = 0; q < QT; q++) {
            float t0 = sc[q * KN + k];
            for (int i = 1; i < S; i++) t0 += sc[q * KN + k + i * Kp];
            s[q] = t0;
        }
        __syncthreads();
    }

    // ---- shift-free softmax: p = exp(s) for valid keys, 0 otherwise ----
    const bool valid_key = (tid < vlen);
    float p[QT];
    #pragma unroll
    for (int q = 0; q < QT; q++)
        p[q] = valid_key ? ex2f(s[q] * LOG2E) : 0.f;

    // prefetch first phase-2 value batch (independent of sc)
    const int v = tid & 127, g = tid >> 7;
    const float* vp = values + (size_t)(b * KN + g * 128) * DD + v;
    int rem = vlen - g * 128;
    int kklim = rem >= 128 ? 128 : (rem > 0 ? ((rem + 7) & ~7) : 0);
    float vv0[8];
    if (kklim > 0) {
        #pragma unroll
        for (int j = 0; j < 8; j++)
            vv0[j] = vp[(size_t)j * DD];
    }

    {   // sum reduction
        float sm[QT];
        #pragma unroll
        for (int q = 0; q < QT; q++) sm[q] = p[q];
        #pragma unroll
        for (int off = 16; off; off >>= 1)
            #pragma unroll
            for (int q = 0; q < QT; q++)
                sm[q] += __shfl_xor_sync(0xFFFFFFFFu, sm[q], off);
        if ((tid & 31) == 0)
            #pragma unroll
            for (int q = 0; q < QT; q++) redv[q * 16 + (tid >> 5)] = sm[q];
    }
    __syncthreads();
    if (tid < 128) {
        int q = tid >> 4, w = tid & 15;
        float t = redv[q * 16 + w];
        #pragma unroll
        for (int off = 8; off; off >>= 1)
            t += __shfl_xor_sync(0xFFFFFFFFu, t, off);
        if (w == 0) sinv[q] = 1.0f / t;
    }
    __syncthreads();
    #pragma unroll
    for (int q = 0; q < QT; q++) sc[q * KN + tid] = p[q] * sinv[q];
    __syncthreads();

    // ---- phase 2: out = attn @ values; first batch prefetched ----
    {
        float a[QT];
        #pragma unroll
        for (int q = 0; q < QT; q++) a[q] = 0.f;

        if (kklim > 0) {
            const int ki0 = g * 128;
            #pragma unroll
            for (int q = 0; q < QT; q++) {
                float4 c0 = *(const float4*)&sc[q * KN + ki0];
                float4 c1 = *(const float4*)&sc[q * KN + ki0 + 4];
                a[q] = fmaf(c0.x, vv0[0], a[q]);
                a[q] = fmaf(c0.y, vv0[1], a[q]);
                a[q] = fmaf(c0.z, vv0[2], a[q]);
                a[q] = fmaf(c0.w, vv0[3], a[q]);
                a[q] = fmaf(c1.x, vv0[4], a[q]);
                a[q] = fmaf(c1.y, vv0[5], a[q]);
                a[q] = fmaf(c1.z, vv0[6], a[q]);
                a[q] = fmaf(c1.w, vv0[7], a[q]);
            }
        }

        #pragma unroll 1
        for (int kk = 8; kk < kklim; kk += 8) {
            float vv[8];
            #pragma unroll
            for (int j = 0; j < 8; j++)
                vv[j] = vp[(size_t)(kk + j) * DD];
            const int ki = g * 128 + kk;
            #pragma unroll
            for (int q = 0; q < QT; q++) {
                float4 c0 = *(const float4*)&sc[q * KN + ki];
                float4 c1 = *(const float4*)&sc[q * KN + ki + 4];
                a[q] = fmaf(c0.x, vv[0], a[q]);
                a[q] = fmaf(c0.y, vv[1], a[q]);
                a[q] = fmaf(c0.z, vv[2], a[q]);
                a[q] = fmaf(c0.w, vv[3], a[q]);
                a[q] = fmaf(c1.x, vv[4], a[q]);
                a[q] = fmaf(c1.y, vv[5], a[q]);
                a[q] = fmaf(c1.z, vv[6], a[q]);
                a[q] = fmaf(c1.w, vv[7], a[q]);
            }
        }
        #pragma unroll
        for (int q = 0; q < QT; q++) part[q * 512 + tid] = a[q];
    }
    __syncthreads();
    #pragma unroll
    for (int i = 0; i < 2; i++) {
        int t = tid + i * 512;
        int q = t >> 7, vo = t & 127;
        const float* pq = &part[q * 512];
        out[(size_t)(b * QN + q0 + q) * DD + vo] =
            (pq[vo] + pq[128 + vo]) + (pq[256 + vo] + pq[384 + vo]);
    }
}

extern "C" void kernel_launch(void* const* d_in, const int* in_sizes, int n_in,
                              void* d_out, int out_size)
{
    const float* queries = (const float*)d_in[0];
    const float* keys    = (const float*)d_in[1];
    const float* values  = (const float*)d_in[2];
    const int*   vlens   = (const int*)  d_in[3];
    const float* Wq      = (const float*)d_in[4];
    const float* Wk      = (const float*)d_in[5];
    const float* wv      = (const float*)d_in[6];
    float* out = (float*)d_out;

    proj_kernel<<<dim3(KN / RT + QN / RT, BB), 512>>>(keys, queries, Wk, Wq, vlens);
    attn_kernel<<<(QN / QT) * BB, 512>>>(values, vlens, wv, out);
}